// round 14
// baseline (speedup 1.0000x reference)
#include <cuda_runtime.h>
#include <cuda_fp16.h>
#include <cstdint>

// Problem constants
#define Bb 4
#define Tt 4096
#define Dd 1024
#define Hh 16
#define Cc 64
#define nCh 64
#define BHt 64
#define Mrows (Bb*Tt)   // 16384

// Scratch (__device__ globals per allocation rules)
__device__ __half g_out_h[Bb*Tt*Dd];     // fp16 input
__device__ __half g_Ww_h[Dd*Dd];
__device__ __half g_Wr_h[Dd*Dd];
__device__ __half g_v_h[Bb*Tt*Dd];       // fp16 write projection
__device__ __half g_intra_h[Bb*Tt*Dd];   // alpha*intra fp16
__device__ __half g_Z_h[BHt*nCh*64*64];  // fp16 chunk increments Z
__device__ __half g_W_h[BHt*nCh*64*64];  // fp16 per-chunk W states
__device__ __half g_reads_h[Bb*Tt*Dd];   // fp16 reads (GEMM2 A)

extern __shared__ float gsm[];

// ---------------------------------------------------------------------------
// helpers
// ---------------------------------------------------------------------------
__device__ __forceinline__ void cp16g(void* sdst, const void* gsrc) {
    unsigned s = (unsigned)__cvta_generic_to_shared(sdst);
    asm volatile("cp.async.ca.shared.global [%0], [%1], 16;" :: "r"(s), "l"(gsrc));
}
__device__ __forceinline__ void cp16s(uint32_t sdst, const void* gsrc) {
    asm volatile("cp.async.ca.shared.global [%0], [%1], 16;" :: "r"(sdst), "l"(gsrc));
}
__device__ __forceinline__ void ldsm4(uint32_t addr, uint32_t& r0, uint32_t& r1,
                                      uint32_t& r2, uint32_t& r3) {
    asm volatile("ldmatrix.sync.aligned.m8n8.x4.shared.b16 {%0,%1,%2,%3}, [%4];"
        : "=r"(r0), "=r"(r1), "=r"(r2), "=r"(r3) : "r"(addr));
}
__device__ __forceinline__ void ldsm4t(uint32_t addr, uint32_t& r0, uint32_t& r1,
                                       uint32_t& r2, uint32_t& r3) {
    asm volatile("ldmatrix.sync.aligned.m8n8.x4.trans.shared.b16 {%0,%1,%2,%3}, [%4];"
        : "=r"(r0), "=r"(r1), "=r"(r2), "=r"(r3) : "r"(addr));
}
__device__ __forceinline__ void mma_f16(float c[4], uint32_t a0, uint32_t a1,
                                        uint32_t a2, uint32_t a3,
                                        uint32_t b0, uint32_t b1) {
    asm volatile(
        "mma.sync.aligned.m16n8k16.row.col.f32.f16.f16.f32 "
        "{%0,%1,%2,%3}, {%4,%5,%6,%7}, {%8,%9}, {%0,%1,%2,%3};"
        : "+f"(c[0]), "+f"(c[1]), "+f"(c[2]), "+f"(c[3])
        : "r"(a0), "r"(a1), "r"(a2), "r"(a3), "r"(b0), "r"(b1));
}

// ---------------------------------------------------------------------------
// fused fp32 -> fp16 conversion for out + W_write + W_read (one launch)
// ---------------------------------------------------------------------------
#define N4_OUT (Bb*Tt*Dd/4)   // 1048576
#define N4_W   (Dd*Dd/4)      // 262144
__global__ __launch_bounds__(256) void cvt_all_f2h(
    const float4* __restrict__ outp, const float4* __restrict__ Ww,
    const float4* __restrict__ Wr, __half2* __restrict__ outh,
    __half2* __restrict__ wwh, __half2* __restrict__ wrh)
{
    int i = blockIdx.x * blockDim.x + threadIdx.x;
    const float4* src;
    __half2* dst;
    int j;
    if (i < N4_OUT)             { src = outp; dst = outh; j = i; }
    else if (i < N4_OUT + N4_W) { src = Ww;   dst = wwh;  j = i - N4_OUT; }
    else if (i < N4_OUT + 2*N4_W) { src = Wr; dst = wrh;  j = i - N4_OUT - N4_W; }
    else return;
    float4 v = src[j];
    dst[j*2]   = __floats2half2_rn(v.x, v.y);
    dst[j*2+1] = __floats2half2_rn(v.z, v.w);
}

// ===========================================================================
// fp16 tensor-core GEMM (NT): BM=BN=128, BK=32, 3-stage, strength-reduced.
// (R9 config — measured plateau 116.5us.)
// ===========================================================================
#define HSTR 40
#define HSTAGE (128*HSTR)
#define NSTG 3
#define GEMM_SMEM (NSTG*2*HSTAGE*(int)sizeof(__half))   // 61440 B

__global__ __launch_bounds__(256, 2) void h16_gemm_nt(
    const __half* __restrict__ A,
    const __half* __restrict__ B,
    const float* __restrict__ Cin,
    void* __restrict__ CoutV,
    int Nn, int K, int addC, int outHalf)
{
    __half* hsm = (__half*)gsm;
    const int tid  = threadIdx.x;
    const int lane = tid & 31;
    const int w    = tid >> 5;
    const int wm   = w >> 2;
    const int wn   = w & 3;
    const int gid  = lane >> 2;
    const int t4   = lane & 3;

    const int bm = blockIdx.y * 128;
    const int bn = blockIdx.x * 128;
    const uint32_t sb = (uint32_t)__cvta_generic_to_shared(hsm);

    float acc[4][4][4];
#pragma unroll
    for (int i = 0; i < 4; i++)
#pragma unroll
        for (int j = 0; j < 4; j++)
#pragma unroll
            for (int q = 0; q < 4; q++) acc[i][j][q] = 0.f;

    const int NIT = K / 32;

    const int cr = tid >> 2;
    const int cc = (tid & 3) * 8;
    const __half* gA0 = A + (size_t)(bm + cr) * K + cc;
    const __half* gA1 = A + (size_t)(bm + cr + 64) * K + cc;
    const __half* gB0 = B + (size_t)(bn + cr) * K + cc;
    const __half* gB1 = B + (size_t)(bn + cr + 64) * K + cc;
    const uint32_t sA0 = sb + (cr * HSTR + cc) * 2;
    const uint32_t sA1 = sb + ((cr + 64) * HSTR + cc) * 2;
    const uint32_t sB0 = sb + (NSTG*HSTAGE + cr * HSTR + cc) * 2;
    const uint32_t sB1 = sb + (NSTG*HSTAGE + (cr + 64) * HSTR + cc) * 2;

    auto copy_stage = [&](int it, int st) {
        const uint32_t so = (uint32_t)(st * HSTAGE) * 2;
        const int ko = it * 32;
        cp16s(sA0 + so, gA0 + ko);
        cp16s(sA1 + so, gA1 + ko);
        cp16s(sB0 + so, gB0 + ko);
        cp16s(sB1 + so, gB1 + ko);
    };

    copy_stage(0, 0);
    asm volatile("cp.async.commit_group;");
    copy_stage(1, 1);
    asm volatile("cp.async.commit_group;");

    const int lrow = lane & 15;
    const int lcol = (lane >> 4) * 8;
    uint32_t aoff[4], boff[2];
#pragma unroll
    for (int i = 0; i < 4; i++)
        aoff[i] = sb + ((wm*64 + i*16 + lrow) * HSTR + lcol) * 2;
#pragma unroll
    for (int p = 0; p < 2; p++)
        boff[p] = sb + (NSTG*HSTAGE + (wn*32 + p*16 + lrow) * HSTR + lcol) * 2;

    for (int it = 0; it < NIT; it++) {
        asm volatile("cp.async.wait_group 1;");
        __syncthreads();
        const uint32_t so = (uint32_t)((it % NSTG) * HSTAGE) * 2;

#pragma unroll
        for (int kk = 0; kk < 2; kk++) {
            const uint32_t ko = so + kk * 32;
            uint32_t af[4][4], bf[4][2];
#pragma unroll
            for (int i = 0; i < 4; i++)
                ldsm4(aoff[i] + ko, af[i][0], af[i][1], af[i][2], af[i][3]);
#pragma unroll
            for (int p = 0; p < 2; p++) {
                uint32_t r0, r1, r2, r3;
                ldsm4(boff[p] + ko, r0, r1, r2, r3);
                bf[2*p  ][0] = r0; bf[2*p+1][0] = r1;
                bf[2*p  ][1] = r2; bf[2*p+1][1] = r3;
            }
#pragma unroll
            for (int i = 0; i < 4; i++)
#pragma unroll
                for (int j = 0; j < 4; j++)
                    mma_f16(acc[i][j], af[i][0], af[i][1], af[i][2], af[i][3],
                            bf[j][0], bf[j][1]);
        }
        if (it + 2 < NIT) copy_stage(it + 2, (it + 2) % NSTG);
        asm volatile("cp.async.commit_group;");
    }

#pragma unroll
    for (int i = 0; i < 4; i++) {
        int row = bm + wm*64 + i*16 + gid;
#pragma unroll
        for (int j = 0; j < 4; j++) {
            int col = bn + wn*32 + j*8 + t4*2;
            float2 r01 = make_float2(acc[i][j][0], acc[i][j][1]);
            float2 r23 = make_float2(acc[i][j][2], acc[i][j][3]);
            if (addC) {
                float2 c01 = *(const float2*)&Cin[(size_t)row*Nn + col];
                float2 c23 = *(const float2*)&Cin[(size_t)(row+8)*Nn + col];
                r01.x += c01.x; r01.y += c01.y;
                r23.x += c23.x; r23.y += c23.y;
            }
            if (outHalf) {
                __half* Ch = (__half*)CoutV;
                *(__half2*)&Ch[(size_t)row*Nn + col]     = __floats2half2_rn(r01.x, r01.y);
                *(__half2*)&Ch[(size_t)(row+8)*Nn + col] = __floats2half2_rn(r23.x, r23.y);
            } else {
                float* Cf = (float*)CoutV;
                *(float2*)&Cf[(size_t)row*Nn + col]     = r01;
                *(float2*)&Cf[(size_t)(row+8)*Nn + col] = r23;
            }
        }
    }
}

// ===========================================================================
// Scan phase A (tensor cores, 128 thr): persistent over NCPB=4 chunks with
// double-buffered cp.async prefetch (chunk i+1 loads overlap chunk i compute).
// Per-buffer: 65-row rkw (wk=row c, rk=row c+1) + 64-row v. Shared S region.
// ===========================================================================
#define TSTR 72
#define NCPB 4
#define RBA ((65+64)*TSTR)                  // halves per buffer (phaseA)
#define PA_SMEM ((2*RBA + 64*TSTR)*2 + 256) // 46624 B
#define RBC (2*64*TSTR)                     // halves per buffer (phaseC)
#define PC_SMEM (2*RBC*2 + 256)             // 37120 B

__global__ __launch_bounds__(128) void scan_phaseA_mma(
    const __half* __restrict__ outh, const __half* __restrict__ vh,
    const float* __restrict__ decay, const float* __restrict__ log_alpha,
    __half* __restrict__ intra, __half* __restrict__ Zh)
{
    __half* smh = (__half*)gsm;
    float*  sgp = (float*)(smh + 2*RBA + 64*TSTR);

    const int tid = threadIdx.x, lane = tid & 31, w = tid >> 5;
    const int c0 = blockIdx.x * NCPB;
    const int bh = blockIdx.y;
    const int b = bh >> 4, h = bh & 15;
    const float gamma = 1.f/(1.f+expf(-decay[h]));
    const float alpha = expf(log_alpha[h]);
    if (tid < 64) sgp[tid] = powf(gamma, (float)tid);

    const __half* obase = outh + (size_t)b*Tt*Dd + h*64;
    const __half* vbs   = vh   + (size_t)b*Tt*Dd + h*64;

    auto load_chunk = [&](int c, int buf) {
        __half* sRKW = smh + buf*RBA;
        __half* sV   = sRKW + 65*TSTR;
        const int t0 = c*64;
#pragma unroll
        for (int i = 0; i < 5; i++) {
            int idx = tid + i*128;
            if (idx < 520) {
                int r = idx >> 3;
                int c8 = (idx & 7)*8;
                long gr = (long)(t0 + r) - 1;
                if (gr < 0) gr = 0;
                cp16g(sRKW + r*TSTR + c8, obase + gr*(long)Dd + c8);
            }
        }
#pragma unroll
        for (int i = 0; i < 4; i++) {
            int idx = tid + i*128;
            int r = idx >> 3;
            int c8 = (idx & 7)*8;
            cp16g(sV + r*TSTR + c8, vbs + (size_t)(t0 + r)*Dd + c8);
        }
    };

    load_chunk(c0, 0);
    asm volatile("cp.async.commit_group;");

    const int lr = lane & 15;
    const int lc = (lane >> 4) * 8;
    const int trr = (lane & 7) + 8*(lane >> 4);
    const int trc = 8*((lane >> 3) & 1);
    const int gid = lane >> 2, t4 = lane & 3;
    const int cc0 = 16*w + gid;

    const uint32_t sbb = (uint32_t)__cvta_generic_to_shared((void*)smh);
    const uint32_t aS  = sbb + (2*RBA)*2;
    __half* sS = smh + 2*RBA;

    for (int i = 0; i < NCPB; i++) {
        const int c = c0 + i;
        const int buf = i & 1;
        const int t0 = c*64;

        __syncthreads();   // prior iter done reading buf^1 before prefetch
        if (i + 1 < NCPB) load_chunk(c + 1, buf ^ 1);
        asm volatile("cp.async.commit_group;");
        if (i + 1 < NCPB) { asm volatile("cp.async.wait_group 1;"); }
        else              { asm volatile("cp.async.wait_group 0;"); }
        __syncthreads();

        const uint32_t bbase = sbb + (buf*RBA)*2;
        const uint32_t aWK = bbase;
        const uint32_t aRK = bbase + TSTR*2;
        const uint32_t aV  = bbase + 65*TSTR*2;
        __half* sV = smh + buf*RBA + 65*TSTR;

        if (c == 0) {
            if (tid < 8)
                *(uint4*)(smh + buf*RBA + tid*8) = make_uint4(0u,0u,0u,0u);
            __syncthreads();
        }

        // ---- S = rk @ wk^T -> sS (masked fp16) ----
        {
            float acc[8][4];
#pragma unroll
            for (int n = 0; n < 8; n++)
                acc[n][0]=acc[n][1]=acc[n][2]=acc[n][3]=0.f;
#pragma unroll
            for (int k = 0; k < 4; k++) {
                int k0 = k*16;
                uint32_t a0,a1,a2,a3;
                ldsm4(aRK + ((16*w + lr)*TSTR + k0 + lc)*2, a0,a1,a2,a3);
#pragma unroll
                for (int np = 0; np < 4; np++) {
                    uint32_t b0,b1,b2,b3;
                    ldsm4(aWK + ((np*16 + lr)*TSTR + k0 + lc)*2, b0,b1,b2,b3);
                    mma_f16(acc[2*np],   a0,a1,a2,a3, b0,b2);
                    mma_f16(acc[2*np+1], a0,a1,a2,a3, b1,b3);
                }
            }
#pragma unroll
            for (int nt = 0; nt < 8; nt++) {
                int kk = nt*8 + 2*t4;
                float m00 = (cc0   > kk  ) ? sgp[cc0-1-kk] : 0.f;
                float m01 = (cc0   > kk+1) ? sgp[cc0-2-kk] : 0.f;
                float m10 = (cc0+8 > kk  ) ? sgp[cc0+7-kk] : 0.f;
                float m11 = (cc0+8 > kk+1) ? sgp[cc0+6-kk] : 0.f;
                *(__half2*)(sS + (size_t)cc0*TSTR + kk) =
                    __floats2half2_rn(acc[nt][0]*m00, acc[nt][1]*m01);
                *(__half2*)(sS + (size_t)(cc0+8)*TSTR + kk) =
                    __floats2half2_rn(acc[nt][2]*m10, acc[nt][3]*m11);
            }
        }
        __syncthreads();

        // ---- intra = alpha * S @ v ----
        {
            float iacc[8][4];
#pragma unroll
            for (int n = 0; n < 8; n++)
                iacc[n][0]=iacc[n][1]=iacc[n][2]=iacc[n][3]=0.f;
#pragma unroll
            for (int k = 0; k < 4; k++) {
                int k0 = k*16;
                uint32_t a0,a1,a2,a3;
                ldsm4(aS + ((16*w + lr)*TSTR + k0 + lc)*2, a0,a1,a2,a3);
#pragma unroll
                for (int np = 0; np < 4; np++) {
                    uint32_t b0,b1,b2,b3;
                    ldsm4t(aV + ((k0 + trr)*TSTR + np*16 + trc)*2, b0,b1,b2,b3);
                    mma_f16(iacc[2*np],   a0,a1,a2,a3, b0,b2);
                    mma_f16(iacc[2*np+1], a0,a1,a2,a3, b1,b3);
                }
            }
            __half* ibase = intra + ((size_t)b*Tt + t0)*Dd + h*64;
#pragma unroll
            for (int nt = 0; nt < 8; nt++) {
                int col = nt*8 + 2*t4;
                *(__half2*)&ibase[(size_t)cc0*Dd + col] =
                    __floats2half2_rn(alpha*iacc[nt][0], alpha*iacc[nt][1]);
                *(__half2*)&ibase[(size_t)(cc0+8)*Dd + col] =
                    __floats2half2_rn(alpha*iacc[nt][2], alpha*iacc[nt][3]);
            }
        }
        __syncthreads();

        // vg -> sS region (reads sV)
#pragma unroll
        for (int q = 0; q < 16; q++) {
            int idx = tid + q*128;
            int row = idx >> 5, col2 = idx & 31;
            __half2 g2 = __float2half2_rn(sgp[63 - row]);
            ((__half2*)sS)[row*(TSTR/2) + col2] =
                __hmul2(((__half2*)sV)[row*(TSTR/2) + col2], g2);
        }
        __syncthreads();

        // ---- Z = vg^T @ wk -> fp16 ----
        {
            float zacc[8][4];
#pragma unroll
            for (int n = 0; n < 8; n++)
                zacc[n][0]=zacc[n][1]=zacc[n][2]=zacc[n][3]=0.f;
#pragma unroll
            for (int k = 0; k < 4; k++) {
                int k0 = k*16;
                uint32_t a0,a1,a2,a3;
                ldsm4t(aS + ((k0 + trr)*TSTR + 16*w + trc)*2, a0,a1,a2,a3);
#pragma unroll
                for (int np = 0; np < 4; np++) {
                    uint32_t b0,b1,b2,b3;
                    ldsm4t(aWK + ((k0 + trr)*TSTR + np*16 + trc)*2, b0,b1,b2,b3);
                    mma_f16(zacc[2*np],   a0,a1,a2,a3, b0,b2);
                    mma_f16(zacc[2*np+1], a0,a1,a2,a3, b1,b3);
                }
            }
            __half* zbase = Zh + ((size_t)bh*nCh + c)*4096;
#pragma unroll
            for (int nt = 0; nt < 8; nt++) {
                int col = nt*8 + 2*t4;
                *(__half2*)&zbase[cc0*64 + col] =
                    __floats2half2_rn(zacc[nt][0], zacc[nt][1]);
                *(__half2*)&zbase[(cc0+8)*64 + col] =
                    __floats2half2_rn(zacc[nt][2], zacc[nt][3]);
            }
        }
    }
}

// ===========================================================================
// Scan phase B: decayed exclusive prefix, 2 elems/thread (__half2), fp32
// accumulators, unroll 8 for MLP. grid (8, BHt) x 256 thr.
// ===========================================================================
__global__ __launch_bounds__(256) void scan_phaseB(
    const float* __restrict__ decay, const __half* __restrict__ Zh,
    __half* __restrict__ Wh)
{
    const int bh = blockIdx.y, h = bh & 15;
    const int e2 = (blockIdx.x * 256 + threadIdx.x) * 2;
    const float gamma = 1.f/(1.f+expf(-decay[h]));
    const float gC = powf(gamma, 64.f);
    float w0 = 0.f, w1 = 0.f;
    size_t base = (size_t)bh*nCh*4096 + e2;
    const __half2* zp = (const __half2*)(Zh + base);
    __half2* wp = (__half2*)(Wh + base);
#pragma unroll 8
    for (int n = 0; n < nCh; n++) {
        __half2 zu = zp[n*2048];
        wp[n*2048] = __floats2half2_rn(w0, w1);
        float2 z = __half22float2(zu);
        w0 = gC*w0 + z.x;
        w1 = gC*w1 + z.y;
    }
}

// ===========================================================================
// Scan phase C (tensor cores, 128 thr): persistent over NCPB chunks,
// double-buffered prefetch. inter = rk @ W^T; reads = intra + alpha*g_p*inter.
// ===========================================================================
__global__ __launch_bounds__(128) void scan_phaseC_mma(
    const __half* __restrict__ outh, const __half* __restrict__ Wh,
    const float* __restrict__ decay, const float* __restrict__ log_alpha,
    const __half* __restrict__ intra, __half* __restrict__ readsh)
{
    __half* smh = (__half*)gsm;
    float*  sgp = (float*)(smh + 2*RBC);

    const int tid = threadIdx.x, lane = tid & 31, w = tid >> 5;
    const int c0 = blockIdx.x * NCPB;
    const int bh = blockIdx.y;
    const int b = bh >> 4, h = bh & 15;
    const float gamma = 1.f/(1.f+expf(-decay[h]));
    const float alpha = expf(log_alpha[h]);
    if (tid < 64) sgp[tid] = powf(gamma, (float)tid);

    const __half* obase = outh + (size_t)b*Tt*Dd + h*64;
    const __half* wbase = Wh + (size_t)bh*nCh*4096;

    auto load_chunk = [&](int c, int buf) {
        __half* sRK = smh + buf*RBC;
        __half* sW  = sRK + 64*TSTR;
        const int t0 = c*64;
        const __half* wsrc = wbase + (size_t)c*4096;
#pragma unroll
        for (int i = 0; i < 4; i++) {
            int idx = tid + i*128;
            int r = idx >> 3;
            int c8 = (idx & 7)*8;
            cp16g(sRK + r*TSTR + c8, obase + (size_t)(t0 + r)*Dd + c8);
            cp16g(sW  + r*TSTR + c8, wsrc + r*64 + c8);
        }
    };

    load_chunk(c0, 0);
    asm volatile("cp.async.commit_group;");

    const int lr = lane & 15;
    const int lc = (lane >> 4) * 8;
    const int gid = lane >> 2, t4 = lane & 3;
    const int cc0 = 16*w + gid;

    const uint32_t sbb = (uint32_t)__cvta_generic_to_shared((void*)smh);

    for (int i = 0; i < NCPB; i++) {
        const int c = c0 + i;
        const int buf = i & 1;
        const int t0 = c*64;

        __syncthreads();
        if (i + 1 < NCPB) load_chunk(c + 1, buf ^ 1);
        asm volatile("cp.async.commit_group;");
        if (i + 1 < NCPB) { asm volatile("cp.async.wait_group 1;"); }
        else              { asm volatile("cp.async.wait_group 0;"); }
        __syncthreads();

        const uint32_t aRK = sbb + (buf*RBC)*2;
        const uint32_t aW  = aRK + 64*TSTR*2;

        float acc[8][4];
#pragma unroll
        for (int n = 0; n < 8; n++)
            acc[n][0]=acc[n][1]=acc[n][2]=acc[n][3]=0.f;
#pragma unroll
        for (int k = 0; k < 4; k++) {
            int k0 = k*16;
            uint32_t a0,a1,a2,a3;
            ldsm4(aRK + ((16*w + lr)*TSTR + k0 + lc)*2, a0,a1,a2,a3);
#pragma unroll
            for (int np = 0; np < 4; np++) {
                uint32_t b0,b1,b2,b3;
                ldsm4(aW + ((np*16 + lr)*TSTR + k0 + lc)*2, b0,b1,b2,b3);
                mma_f16(acc[2*np],   a0,a1,a2,a3, b0,b2);
                mma_f16(acc[2*np+1], a0,a1,a2,a3, b1,b3);
            }
        }

        const __half* ibase = intra + ((size_t)b*Tt + t0)*Dd + h*64;
        __half* rdst = readsh + ((size_t)b*Tt + t0)*Dd + h*64;
        const float gp0 = alpha * sgp[cc0];
        const float gp1 = alpha * sgp[cc0 + 8];
#pragma unroll
        for (int nt = 0; nt < 8; nt++) {
            int col = nt*8 + 2*t4;
            float2 i0 = __half22float2(*(const __half2*)&ibase[(size_t)cc0*Dd + col]);
            float2 i1 = __half22float2(*(const __half2*)&ibase[(size_t)(cc0+8)*Dd + col]);
            *(__half2*)&rdst[(size_t)cc0*Dd + col] =
                __floats2half2_rn(i0.x + gp0*acc[nt][0], i0.y + gp0*acc[nt][1]);
            *(__half2*)&rdst[(size_t)(cc0+8)*Dd + col] =
                __floats2half2_rn(i1.x + gp1*acc[nt][2], i1.y + gp1*acc[nt][3]);
        }
    }
}

// ===========================================================================
extern "C" void kernel_launch(void* const* d_in, const int* in_sizes, int n_in,
                              void* d_out, int out_size)
{
    const float* outp      = (const float*)d_in[0];
    const float* W_write   = (const float*)d_in[1];
    const float* W_read    = (const float*)d_in[2];
    const float* decay     = (const float*)d_in[3];
    const float* log_alpha = (const float*)d_in[4];
    float* result = (float*)d_out;

    __half *outh, *wwh, *wrh, *vh, *ih, *zh, *whs, *readsh;
    cudaGetSymbolAddress((void**)&outh,   g_out_h);
    cudaGetSymbolAddress((void**)&wwh,    g_Ww_h);
    cudaGetSymbolAddress((void**)&wrh,    g_Wr_h);
    cudaGetSymbolAddress((void**)&vh,     g_v_h);
    cudaGetSymbolAddress((void**)&ih,     g_intra_h);
    cudaGetSymbolAddress((void**)&zh,     g_Z_h);
    cudaGetSymbolAddress((void**)&whs,    g_W_h);
    cudaGetSymbolAddress((void**)&readsh, g_reads_h);

    cudaFuncSetAttribute(h16_gemm_nt,
        cudaFuncAttributeMaxDynamicSharedMemorySize, GEMM_SMEM);
    cudaFuncSetAttribute(scan_phaseA_mma,
        cudaFuncAttributeMaxDynamicSharedMemorySize, PA_SMEM);
    cudaFuncSetAttribute(scan_phaseC_mma,
        cudaFuncAttributeMaxDynamicSharedMemorySize, PC_SMEM);

    // fused conversions (one launch)
    const int totN4 = N4_OUT + 2*N4_W;
    cvt_all_f2h<<<(totN4 + 255)/256, 256>>>(
        (const float4*)outp, (const float4*)W_write, (const float4*)W_read,
        (__half2*)outh, (__half2*)wwh, (__half2*)wrh);

    dim3 gemm_grid(Dd/128, Mrows/128);   // (8, 128)

    // GEMM1: v_h = fp16(out @ W_write^T)
    h16_gemm_nt<<<gemm_grid, 256, GEMM_SMEM>>>(outh, wwh, nullptr, vh,
                                               Dd, Dd, 0, 1);
    // Scan
    scan_phaseA_mma<<<dim3(nCh/NCPB, BHt), 128, PA_SMEM>>>(outh, vh, decay,
                                                           log_alpha, ih, zh);
    scan_phaseB<<<dim3(8, BHt), 256>>>(decay, zh, whs);
    scan_phaseC_mma<<<dim3(nCh/NCPB, BHt), 128, PC_SMEM>>>(outh, whs, decay,
                                                           log_alpha, ih, readsh);
    // GEMM2: result = out + reads @ W_read^T (fp32 out)
    h16_gemm_nt<<<gemm_grid, 256, GEMM_SMEM>>>(readsh, wrh, outp, result,
                                               Dd, Dd, 1, 0);
}

// round 15
// speedup vs baseline: 1.0222x; 1.0222x over previous
#include <cuda_runtime.h>
#include <cuda_fp16.h>
#include <cstdint>

// Problem constants
#define Bb 4
#define Tt 4096
#define Dd 1024
#define Hh 16
#define Cc 64
#define nCh 64
#define BHt 64
#define Mrows (Bb*Tt)   // 16384

// Scratch (__device__ globals per allocation rules)
__device__ __half g_out_h[Bb*Tt*Dd];     // fp16 input
__device__ __half g_Ww_h[Dd*Dd];
__device__ __half g_Wr_h[Dd*Dd];
__device__ __half g_v_h[Bb*Tt*Dd];       // fp16 write projection
__device__ __half g_intra_h[Bb*Tt*Dd];   // alpha*intra fp16
__device__ __half g_Z_h[BHt*nCh*64*64];  // fp16 chunk increments Z
__device__ __half g_W_h[BHt*nCh*64*64];  // fp16 per-chunk W states
__device__ __half g_reads_h[Bb*Tt*Dd];   // fp16 reads (GEMM2 A)

extern __shared__ float gsm[];

// ---------------------------------------------------------------------------
// helpers
// ---------------------------------------------------------------------------
__device__ __forceinline__ void cp16g(void* sdst, const void* gsrc) {
    unsigned s = (unsigned)__cvta_generic_to_shared(sdst);
    asm volatile("cp.async.ca.shared.global [%0], [%1], 16;" :: "r"(s), "l"(gsrc));
}
__device__ __forceinline__ void cp16s(uint32_t sdst, const void* gsrc) {
    asm volatile("cp.async.ca.shared.global [%0], [%1], 16;" :: "r"(sdst), "l"(gsrc));
}
__device__ __forceinline__ void ldsm4(uint32_t addr, uint32_t& r0, uint32_t& r1,
                                      uint32_t& r2, uint32_t& r3) {
    asm volatile("ldmatrix.sync.aligned.m8n8.x4.shared.b16 {%0,%1,%2,%3}, [%4];"
        : "=r"(r0), "=r"(r1), "=r"(r2), "=r"(r3) : "r"(addr));
}
__device__ __forceinline__ void ldsm4t(uint32_t addr, uint32_t& r0, uint32_t& r1,
                                       uint32_t& r2, uint32_t& r3) {
    asm volatile("ldmatrix.sync.aligned.m8n8.x4.trans.shared.b16 {%0,%1,%2,%3}, [%4];"
        : "=r"(r0), "=r"(r1), "=r"(r2), "=r"(r3) : "r"(addr));
}
__device__ __forceinline__ void mma_f16(float c[4], uint32_t a0, uint32_t a1,
                                        uint32_t a2, uint32_t a3,
                                        uint32_t b0, uint32_t b1) {
    asm volatile(
        "mma.sync.aligned.m16n8k16.row.col.f32.f16.f16.f32 "
        "{%0,%1,%2,%3}, {%4,%5,%6,%7}, {%8,%9}, {%0,%1,%2,%3};"
        : "+f"(c[0]), "+f"(c[1]), "+f"(c[2]), "+f"(c[3])
        : "r"(a0), "r"(a1), "r"(a2), "r"(a3), "r"(b0), "r"(b1));
}

// ---------------------------------------------------------------------------
// fused fp32 -> fp16 conversion for out + W_write + W_read (one launch)
// ---------------------------------------------------------------------------
#define N4_OUT (Bb*Tt*Dd/4)   // 1048576
#define N4_W   (Dd*Dd/4)      // 262144
__global__ __launch_bounds__(256) void cvt_all_f2h(
    const float4* __restrict__ outp, const float4* __restrict__ Ww,
    const float4* __restrict__ Wr, __half2* __restrict__ outh,
    __half2* __restrict__ wwh, __half2* __restrict__ wrh)
{
    int i = blockIdx.x * blockDim.x + threadIdx.x;
    const float4* src;
    __half2* dst;
    int j;
    if (i < N4_OUT)             { src = outp; dst = outh; j = i; }
    else if (i < N4_OUT + N4_W) { src = Ww;   dst = wwh;  j = i - N4_OUT; }
    else if (i < N4_OUT + 2*N4_W) { src = Wr; dst = wrh;  j = i - N4_OUT - N4_W; }
    else return;
    float4 v = src[j];
    dst[j*2]   = __floats2half2_rn(v.x, v.y);
    dst[j*2+1] = __floats2half2_rn(v.z, v.w);
}

// ===========================================================================
// fp16 tensor-core GEMM (NT): BM=BN=128, BK=32, 3-stage, strength-reduced.
// (Measured plateau: 116.5us per 16384x1024x1024.)
// ===========================================================================
#define HSTR 40
#define HSTAGE (128*HSTR)
#define NSTG 3
#define GEMM_SMEM (NSTG*2*HSTAGE*(int)sizeof(__half))   // 61440 B

__global__ __launch_bounds__(256, 2) void h16_gemm_nt(
    const __half* __restrict__ A,
    const __half* __restrict__ B,
    const float* __restrict__ Cin,
    void* __restrict__ CoutV,
    int Nn, int K, int addC, int outHalf)
{
    __half* hsm = (__half*)gsm;
    const int tid  = threadIdx.x;
    const int lane = tid & 31;
    const int w    = tid >> 5;
    const int wm   = w >> 2;
    const int wn   = w & 3;
    const int gid  = lane >> 2;
    const int t4   = lane & 3;

    const int bm = blockIdx.y * 128;
    const int bn = blockIdx.x * 128;
    const uint32_t sb = (uint32_t)__cvta_generic_to_shared(hsm);

    float acc[4][4][4];
#pragma unroll
    for (int i = 0; i < 4; i++)
#pragma unroll
        for (int j = 0; j < 4; j++)
#pragma unroll
            for (int q = 0; q < 4; q++) acc[i][j][q] = 0.f;

    const int NIT = K / 32;

    const int cr = tid >> 2;
    const int cc = (tid & 3) * 8;
    const __half* gA0 = A + (size_t)(bm + cr) * K + cc;
    const __half* gA1 = A + (size_t)(bm + cr + 64) * K + cc;
    const __half* gB0 = B + (size_t)(bn + cr) * K + cc;
    const __half* gB1 = B + (size_t)(bn + cr + 64) * K + cc;
    const uint32_t sA0 = sb + (cr * HSTR + cc) * 2;
    const uint32_t sA1 = sb + ((cr + 64) * HSTR + cc) * 2;
    const uint32_t sB0 = sb + (NSTG*HSTAGE + cr * HSTR + cc) * 2;
    const uint32_t sB1 = sb + (NSTG*HSTAGE + (cr + 64) * HSTR + cc) * 2;

    auto copy_stage = [&](int it, int st) {
        const uint32_t so = (uint32_t)(st * HSTAGE) * 2;
        const int ko = it * 32;
        cp16s(sA0 + so, gA0 + ko);
        cp16s(sA1 + so, gA1 + ko);
        cp16s(sB0 + so, gB0 + ko);
        cp16s(sB1 + so, gB1 + ko);
    };

    copy_stage(0, 0);
    asm volatile("cp.async.commit_group;");
    copy_stage(1, 1);
    asm volatile("cp.async.commit_group;");

    const int lrow = lane & 15;
    const int lcol = (lane >> 4) * 8;
    uint32_t aoff[4], boff[2];
#pragma unroll
    for (int i = 0; i < 4; i++)
        aoff[i] = sb + ((wm*64 + i*16 + lrow) * HSTR + lcol) * 2;
#pragma unroll
    for (int p = 0; p < 2; p++)
        boff[p] = sb + (NSTG*HSTAGE + (wn*32 + p*16 + lrow) * HSTR + lcol) * 2;

    for (int it = 0; it < NIT; it++) {
        asm volatile("cp.async.wait_group 1;");
        __syncthreads();
        const uint32_t so = (uint32_t)((it % NSTG) * HSTAGE) * 2;

#pragma unroll
        for (int kk = 0; kk < 2; kk++) {
            const uint32_t ko = so + kk * 32;
            uint32_t af[4][4], bf[4][2];
#pragma unroll
            for (int i = 0; i < 4; i++)
                ldsm4(aoff[i] + ko, af[i][0], af[i][1], af[i][2], af[i][3]);
#pragma unroll
            for (int p = 0; p < 2; p++) {
                uint32_t r0, r1, r2, r3;
                ldsm4(boff[p] + ko, r0, r1, r2, r3);
                bf[2*p  ][0] = r0; bf[2*p+1][0] = r1;
                bf[2*p  ][1] = r2; bf[2*p+1][1] = r3;
            }
#pragma unroll
            for (int i = 0; i < 4; i++)
#pragma unroll
                for (int j = 0; j < 4; j++)
                    mma_f16(acc[i][j], af[i][0], af[i][1], af[i][2], af[i][3],
                            bf[j][0], bf[j][1]);
        }
        if (it + 2 < NIT) copy_stage(it + 2, (it + 2) % NSTG);
        asm volatile("cp.async.commit_group;");
    }

#pragma unroll
    for (int i = 0; i < 4; i++) {
        int row = bm + wm*64 + i*16 + gid;
#pragma unroll
        for (int j = 0; j < 4; j++) {
            int col = bn + wn*32 + j*8 + t4*2;
            float2 r01 = make_float2(acc[i][j][0], acc[i][j][1]);
            float2 r23 = make_float2(acc[i][j][2], acc[i][j][3]);
            if (addC) {
                float2 c01 = *(const float2*)&Cin[(size_t)row*Nn + col];
                float2 c23 = *(const float2*)&Cin[(size_t)(row+8)*Nn + col];
                r01.x += c01.x; r01.y += c01.y;
                r23.x += c23.x; r23.y += c23.y;
            }
            if (outHalf) {
                __half* Ch = (__half*)CoutV;
                *(__half2*)&Ch[(size_t)row*Nn + col]     = __floats2half2_rn(r01.x, r01.y);
                *(__half2*)&Ch[(size_t)(row+8)*Nn + col] = __floats2half2_rn(r23.x, r23.y);
            } else {
                float* Cf = (float*)CoutV;
                *(float2*)&Cf[(size_t)row*Nn + col]     = r01;
                *(float2*)&Cf[(size_t)(row+8)*Nn + col] = r23;
            }
        }
    }
}

// ===========================================================================
// Scan phase A (tensor cores, 128 thr = 4 warps, one chunk per block).
// 65-row rkw tile (wk = row c, rk = row c+1); S masked -> smem fp16;
// intra = alpha*S@v -> fp16; vg overwrites S; Z = vg^T@wk -> fp16.
// (R9/R10 measured-best configuration.)
// ===========================================================================
#define TSTR 72
#define PA_SMEM ((193*TSTR)*2 + 256)
#define PC_SMEM (2*64*TSTR*2 + 64*4)

__global__ __launch_bounds__(128) void scan_phaseA_mma(
    const __half* __restrict__ outh, const __half* __restrict__ vh,
    const float* __restrict__ decay, const float* __restrict__ log_alpha,
    __half* __restrict__ intra, __half* __restrict__ Zh)
{
    __half* sRKW = (__half*)gsm;            // 65 rows
    __half* sV   = sRKW + 65*TSTR;          // 64 rows
    __half* sS   = sV   + 64*TSTR;          // 64 rows (S, later vg)
    float*  sgp  = (float*)(sS + 64*TSTR);

    const int tid = threadIdx.x, lane = tid & 31, w = tid >> 5;
    const int chunk = blockIdx.x, bh = blockIdx.y;
    const int b = bh >> 4, h = bh & 15;
    const float gamma = 1.f/(1.f+expf(-decay[h]));
    const float alpha = expf(log_alpha[h]);
    if (tid < 64) sgp[tid] = powf(gamma, (float)tid);

    const int t0 = chunk*64;
    const __half* rbase = outh + ((size_t)b*Tt + t0)*Dd + h*64;
    const __half* vbase = vh   + ((size_t)b*Tt + t0)*Dd + h*64;

#pragma unroll
    for (int i = 0; i < 5; i++) {
        int idx = tid + i*128;
        if (idx < 520) {
            int r = idx >> 3;
            int c8 = (idx & 7)*8;
            long gr = (long)r - 1;
            if (t0 + (int)gr < 0) gr = 0;
            cp16g(sRKW + r*TSTR + c8, rbase + gr*(long)Dd + c8);
        }
    }
#pragma unroll
    for (int i = 0; i < 4; i++) {
        int idx = tid + i*128;
        int r = idx >> 3;
        int c8 = (idx & 7)*8;
        cp16g(sV + r*TSTR + c8, vbase + (size_t)r*Dd + c8);
    }
    asm volatile("cp.async.commit_group;");
    asm volatile("cp.async.wait_group 0;");
    __syncthreads();
    if (chunk == 0 && tid < 8)
        *(uint4*)(sRKW + tid*8) = make_uint4(0u,0u,0u,0u);
    __syncthreads();

    const uint32_t sb  = (uint32_t)__cvta_generic_to_shared((void*)sRKW);
    const uint32_t aWK = sb;
    const uint32_t aRK = sb + TSTR*2;
    const uint32_t aV  = sb + 65*TSTR*2;
    const uint32_t aS  = sb + (65+64)*TSTR*2;

    const int lr = lane & 15;
    const int lc = (lane >> 4) * 8;
    const int trr = (lane & 7) + 8*(lane >> 4);
    const int trc = 8*((lane >> 3) & 1);
    const int gid = lane >> 2, t4 = lane & 3;
    const int cc0 = 16*w + gid;

    // ---- S = rk @ wk^T ----
    {
        float acc[8][4];
#pragma unroll
        for (int n = 0; n < 8; n++)
            acc[n][0]=acc[n][1]=acc[n][2]=acc[n][3]=0.f;
#pragma unroll
        for (int k = 0; k < 4; k++) {
            int k0 = k*16;
            uint32_t a0,a1,a2,a3;
            ldsm4(aRK + ((16*w + lr)*TSTR + k0 + lc)*2, a0,a1,a2,a3);
#pragma unroll
            for (int np = 0; np < 4; np++) {
                uint32_t b0,b1,b2,b3;
                ldsm4(aWK + ((np*16 + lr)*TSTR + k0 + lc)*2, b0,b1,b2,b3);
                mma_f16(acc[2*np],   a0,a1,a2,a3, b0,b2);
                mma_f16(acc[2*np+1], a0,a1,a2,a3, b1,b3);
            }
        }
#pragma unroll
        for (int nt = 0; nt < 8; nt++) {
            int kk = nt*8 + 2*t4;
            float m00 = (cc0   > kk  ) ? sgp[cc0-1-kk] : 0.f;
            float m01 = (cc0   > kk+1) ? sgp[cc0-2-kk] : 0.f;
            float m10 = (cc0+8 > kk  ) ? sgp[cc0+7-kk] : 0.f;
            float m11 = (cc0+8 > kk+1) ? sgp[cc0+6-kk] : 0.f;
            *(__half2*)(sS + (size_t)cc0*TSTR + kk) =
                __floats2half2_rn(acc[nt][0]*m00, acc[nt][1]*m01);
            *(__half2*)(sS + (size_t)(cc0+8)*TSTR + kk) =
                __floats2half2_rn(acc[nt][2]*m10, acc[nt][3]*m11);
        }
    }
    __syncthreads();

    // ---- intra = S @ v ----
    {
        float iacc[8][4];
#pragma unroll
        for (int n = 0; n < 8; n++)
            iacc[n][0]=iacc[n][1]=iacc[n][2]=iacc[n][3]=0.f;
#pragma unroll
        for (int k = 0; k < 4; k++) {
            int k0 = k*16;
            uint32_t a0,a1,a2,a3;
            ldsm4(aS + ((16*w + lr)*TSTR + k0 + lc)*2, a0,a1,a2,a3);
#pragma unroll
            for (int np = 0; np < 4; np++) {
                uint32_t b0,b1,b2,b3;
                ldsm4t(aV + ((k0 + trr)*TSTR + np*16 + trc)*2, b0,b1,b2,b3);
                mma_f16(iacc[2*np],   a0,a1,a2,a3, b0,b2);
                mma_f16(iacc[2*np+1], a0,a1,a2,a3, b1,b3);
            }
        }
        __half* ibase = intra + ((size_t)b*Tt + t0)*Dd + h*64;
#pragma unroll
        for (int nt = 0; nt < 8; nt++) {
            int col = nt*8 + 2*t4;
            *(__half2*)&ibase[(size_t)cc0*Dd + col] =
                __floats2half2_rn(alpha*iacc[nt][0], alpha*iacc[nt][1]);
            *(__half2*)&ibase[(size_t)(cc0+8)*Dd + col] =
                __floats2half2_rn(alpha*iacc[nt][2], alpha*iacc[nt][3]);
        }
    }
    __syncthreads();

    // vg -> sS region
#pragma unroll
    for (int i = 0; i < 16; i++) {
        int idx = tid + i*128;
        int row = idx >> 5, col2 = idx & 31;
        __half2 g2 = __float2half2_rn(sgp[63 - row]);
        ((__half2*)sS)[row*(TSTR/2) + col2] =
            __hmul2(((__half2*)sV)[row*(TSTR/2) + col2], g2);
    }
    __syncthreads();

    // ---- Z = vg^T @ wk -> fp16 ----
    {
        float zacc[8][4];
#pragma unroll
        for (int n = 0; n < 8; n++)
            zacc[n][0]=zacc[n][1]=zacc[n][2]=zacc[n][3]=0.f;
#pragma unroll
        for (int k = 0; k < 4; k++) {
            int k0 = k*16;
            uint32_t a0,a1,a2,a3;
            ldsm4t(aS + ((k0 + trr)*TSTR + 16*w + trc)*2, a0,a1,a2,a3);
#pragma unroll
            for (int np = 0; np < 4; np++) {
                uint32_t b0,b1,b2,b3;
                ldsm4t(aWK + ((k0 + trr)*TSTR + np*16 + trc)*2, b0,b1,b2,b3);
                mma_f16(zacc[2*np],   a0,a1,a2,a3, b0,b2);
                mma_f16(zacc[2*np+1], a0,a1,a2,a3, b1,b3);
            }
        }
        __half* zbase = Zh + ((size_t)bh*nCh + chunk)*4096;
#pragma unroll
        for (int nt = 0; nt < 8; nt++) {
            int col = nt*8 + 2*t4;
            *(__half2*)&zbase[cc0*64 + col] =
                __floats2half2_rn(zacc[nt][0], zacc[nt][1]);
            *(__half2*)&zbase[(cc0+8)*64 + col] =
                __floats2half2_rn(zacc[nt][2], zacc[nt][3]);
        }
    }
}

// ===========================================================================
// Scan phase B: decayed exclusive prefix, 2 elems/thread (__half2), fp32
// accumulators, unroll 8 (measured 13.1us). grid (8, BHt) x 256 thr.
// ===========================================================================
__global__ __launch_bounds__(256) void scan_phaseB(
    const float* __restrict__ decay, const __half* __restrict__ Zh,
    __half* __restrict__ Wh)
{
    const int bh = blockIdx.y, h = bh & 15;
    const int e2 = (blockIdx.x * 256 + threadIdx.x) * 2;
    const float gamma = 1.f/(1.f+expf(-decay[h]));
    const float gC = powf(gamma, 64.f);
    float w0 = 0.f, w1 = 0.f;
    size_t base = (size_t)bh*nCh*4096 + e2;
    const __half2* zp = (const __half2*)(Zh + base);
    __half2* wp = (__half2*)(Wh + base);
#pragma unroll 8
    for (int n = 0; n < nCh; n++) {
        __half2 zu = zp[n*2048];
        wp[n*2048] = __floats2half2_rn(w0, w1);
        float2 z = __half22float2(zu);
        w0 = gC*w0 + z.x;
        w1 = gC*w1 + z.y;
    }
}

// ===========================================================================
// Scan phase C (tensor cores, 128 thr, one chunk per block):
//   inter = rk @ W^T ; reads_h = fp16(intra + alpha*g_p[c]*inter)
// ===========================================================================
__global__ __launch_bounds__(128) void scan_phaseC_mma(
    const __half* __restrict__ outh, const __half* __restrict__ Wh,
    const float* __restrict__ decay, const float* __restrict__ log_alpha,
    const __half* __restrict__ intra, __half* __restrict__ readsh)
{
    __half* sRK = (__half*)gsm;
    __half* sW  = sRK + 64*TSTR;
    float*  sgp = (float*)(sW + 64*TSTR);

    const int tid = threadIdx.x, lane = tid & 31, w = tid >> 5;
    const int chunk = blockIdx.x, bh = blockIdx.y;
    const int b = bh >> 4, h = bh & 15;
    const float gamma = 1.f/(1.f+expf(-decay[h]));
    const float alpha = expf(log_alpha[h]);
    if (tid < 64) sgp[tid] = powf(gamma, (float)tid);

    const int t0 = chunk*64;
    const __half* rbase = outh + ((size_t)b*Tt + t0)*Dd + h*64;
    const __half* wsrc  = Wh + ((size_t)bh*nCh + chunk)*4096;

#pragma unroll
    for (int i = 0; i < 4; i++) {
        int idx = tid + i*128;
        int r = idx >> 3;
        int c8 = (idx & 7)*8;
        cp16g(sRK + r*TSTR + c8, rbase + (size_t)r*Dd + c8);
        cp16g(sW  + r*TSTR + c8, wsrc + r*64 + c8);
    }
    asm volatile("cp.async.commit_group;");
    asm volatile("cp.async.wait_group 0;");
    __syncthreads();

    const uint32_t sb  = (uint32_t)__cvta_generic_to_shared((void*)sRK);
    const uint32_t aRK = sb;
    const uint32_t aW  = sb + 64*TSTR*2;

    const int lr = lane & 15;
    const int lc = (lane >> 4) * 8;
    const int gid = lane >> 2, t4 = lane & 3;
    const int cc0 = 16*w + gid;

    float acc[8][4];
#pragma unroll
    for (int n = 0; n < 8; n++)
        acc[n][0]=acc[n][1]=acc[n][2]=acc[n][3]=0.f;
#pragma unroll
    for (int k = 0; k < 4; k++) {
        int k0 = k*16;
        uint32_t a0,a1,a2,a3;
        ldsm4(aRK + ((16*w + lr)*TSTR + k0 + lc)*2, a0,a1,a2,a3);
#pragma unroll
        for (int np = 0; np < 4; np++) {
            uint32_t b0,b1,b2,b3;
            ldsm4(aW + ((np*16 + lr)*TSTR + k0 + lc)*2, b0,b1,b2,b3);
            mma_f16(acc[2*np],   a0,a1,a2,a3, b0,b2);
            mma_f16(acc[2*np+1], a0,a1,a2,a3, b1,b3);
        }
    }

    const __half* ibase = intra + ((size_t)b*Tt + t0)*Dd + h*64;
    __half* obase = readsh + ((size_t)b*Tt + t0)*Dd + h*64;
    const float gp0 = alpha * sgp[cc0];
    const float gp1 = alpha * sgp[cc0 + 8];
#pragma unroll
    for (int nt = 0; nt < 8; nt++) {
        int col = nt*8 + 2*t4;
        float2 i0 = __half22float2(*(const __half2*)&ibase[(size_t)cc0*Dd + col]);
        float2 i1 = __half22float2(*(const __half2*)&ibase[(size_t)(cc0+8)*Dd + col]);
        *(__half2*)&obase[(size_t)cc0*Dd + col] =
            __floats2half2_rn(i0.x + gp0*acc[nt][0], i0.y + gp0*acc[nt][1]);
        *(__half2*)&obase[(size_t)(cc0+8)*Dd + col] =
            __floats2half2_rn(i1.x + gp1*acc[nt][2], i1.y + gp1*acc[nt][3]);
    }
}

// ===========================================================================
extern "C" void kernel_launch(void* const* d_in, const int* in_sizes, int n_in,
                              void* d_out, int out_size)
{
    const float* outp      = (const float*)d_in[0];
    const float* W_write   = (const float*)d_in[1];
    const float* W_read    = (const float*)d_in[2];
    const float* decay     = (const float*)d_in[3];
    const float* log_alpha = (const float*)d_in[4];
    float* result = (float*)d_out;

    __half *outh, *wwh, *wrh, *vh, *ih, *zh, *whs, *readsh;
    cudaGetSymbolAddress((void**)&outh,   g_out_h);
    cudaGetSymbolAddress((void**)&wwh,    g_Ww_h);
    cudaGetSymbolAddress((void**)&wrh,    g_Wr_h);
    cudaGetSymbolAddress((void**)&vh,     g_v_h);
    cudaGetSymbolAddress((void**)&ih,     g_intra_h);
    cudaGetSymbolAddress((void**)&zh,     g_Z_h);
    cudaGetSymbolAddress((void**)&whs,    g_W_h);
    cudaGetSymbolAddress((void**)&readsh, g_reads_h);

    cudaFuncSetAttribute(h16_gemm_nt,
        cudaFuncAttributeMaxDynamicSharedMemorySize, GEMM_SMEM);
    cudaFuncSetAttribute(scan_phaseA_mma,
        cudaFuncAttributeMaxDynamicSharedMemorySize, PA_SMEM);
    cudaFuncSetAttribute(scan_phaseC_mma,
        cudaFuncAttributeMaxDynamicSharedMemorySize, PC_SMEM);

    // fused conversions (one launch)
    const int totN4 = N4_OUT + 2*N4_W;
    cvt_all_f2h<<<(totN4 + 255)/256, 256>>>(
        (const float4*)outp, (const float4*)W_write, (const float4*)W_read,
        (__half2*)outh, (__half2*)wwh, (__half2*)wrh);

    dim3 gemm_grid(Dd/128, Mrows/128);   // (8, 128)

    // GEMM1: v_h = fp16(out @ W_write^T)
    h16_gemm_nt<<<gemm_grid, 256, GEMM_SMEM>>>(outh, wwh, nullptr, vh,
                                               Dd, Dd, 0, 1);
    // Scan
    scan_phaseA_mma<<<dim3(nCh, BHt), 128, PA_SMEM>>>(outh, vh, decay,
                                                      log_alpha, ih, zh);
    scan_phaseB<<<dim3(8, BHt), 256>>>(decay, zh, whs);
    scan_phaseC_mma<<<dim3(nCh, BHt), 128, PC_SMEM>>>(outh, whs, decay,
                                                      log_alpha, ih, readsh);
    // GEMM2: result = out + reads @ W_read^T (fp32 out)
    h16_gemm_nt<<<gemm_grid, 256, GEMM_SMEM>>>(readsh, wrh, outp, result,
                                               Dd, Dd, 1, 0);
}

// round 16
// speedup vs baseline: 1.0286x; 1.0063x over previous
#include <cuda_runtime.h>
#include <cuda_fp16.h>
#include <cstdint>

// Problem constants
#define Bb 4
#define Tt 4096
#define Dd 1024
#define Hh 16
#define Cc 64
#define nCh 64
#define BHt 64
#define Mrows (Bb*Tt)   // 16384

// Scratch (__device__ globals per allocation rules)
__device__ __half g_out_h[Bb*Tt*Dd];     // fp16 input
__device__ __half g_Ww_h[Dd*Dd];
__device__ __half g_Wr_h[Dd*Dd];
__device__ __half g_v_h[Bb*Tt*Dd];       // fp16 write projection
__device__ __half g_intra_h[Bb*Tt*Dd];   // alpha*intra fp16
__device__ __half g_Z_h[BHt*nCh*64*64];  // fp16 chunk increments Z
__device__ __half g_W_h[BHt*nCh*64*64];  // fp16 per-chunk W states
__device__ __half g_reads_h[Bb*Tt*Dd];   // fp16 reads (GEMM2 A)

extern __shared__ float gsm[];

// ---------------------------------------------------------------------------
// helpers
// ---------------------------------------------------------------------------
__device__ __forceinline__ void cp16g(void* sdst, const void* gsrc) {
    unsigned s = (unsigned)__cvta_generic_to_shared(sdst);
    asm volatile("cp.async.ca.shared.global [%0], [%1], 16;" :: "r"(s), "l"(gsrc));
}
__device__ __forceinline__ void cp16s(uint32_t sdst, const void* gsrc) {
    asm volatile("cp.async.ca.shared.global [%0], [%1], 16;" :: "r"(sdst), "l"(gsrc));
}
__device__ __forceinline__ void ldsm4(uint32_t addr, uint32_t& r0, uint32_t& r1,
                                      uint32_t& r2, uint32_t& r3) {
    asm volatile("ldmatrix.sync.aligned.m8n8.x4.shared.b16 {%0,%1,%2,%3}, [%4];"
        : "=r"(r0), "=r"(r1), "=r"(r2), "=r"(r3) : "r"(addr));
}
__device__ __forceinline__ void ldsm4t(uint32_t addr, uint32_t& r0, uint32_t& r1,
                                       uint32_t& r2, uint32_t& r3) {
    asm volatile("ldmatrix.sync.aligned.m8n8.x4.trans.shared.b16 {%0,%1,%2,%3}, [%4];"
        : "=r"(r0), "=r"(r1), "=r"(r2), "=r"(r3) : "r"(addr));
}
__device__ __forceinline__ void mma_f16(float c[4], uint32_t a0, uint32_t a1,
                                        uint32_t a2, uint32_t a3,
                                        uint32_t b0, uint32_t b1) {
    asm volatile(
        "mma.sync.aligned.m16n8k16.row.col.f32.f16.f16.f32 "
        "{%0,%1,%2,%3}, {%4,%5,%6,%7}, {%8,%9}, {%0,%1,%2,%3};"
        : "+f"(c[0]), "+f"(c[1]), "+f"(c[2]), "+f"(c[3])
        : "r"(a0), "r"(a1), "r"(a2), "r"(a3), "r"(b0), "r"(b1));
}

// ---------------------------------------------------------------------------
// fused fp32 -> fp16 conversion for out + W_write + W_read (one launch)
// ---------------------------------------------------------------------------
#define N4_OUT (Bb*Tt*Dd/4)   // 1048576
#define N4_W   (Dd*Dd/4)      // 262144
__global__ __launch_bounds__(256) void cvt_all_f2h(
    const float4* __restrict__ outp, const float4* __restrict__ Ww,
    const float4* __restrict__ Wr, __half2* __restrict__ outh,
    __half2* __restrict__ wwh, __half2* __restrict__ wrh)
{
    int i = blockIdx.x * blockDim.x + threadIdx.x;
    const float4* src;
    __half2* dst;
    int j;
    if (i < N4_OUT)             { src = outp; dst = outh; j = i; }
    else if (i < N4_OUT + N4_W) { src = Ww;   dst = wwh;  j = i - N4_OUT; }
    else if (i < N4_OUT + 2*N4_W) { src = Wr; dst = wrh;  j = i - N4_OUT - N4_W; }
    else return;
    float4 v = src[j];
    dst[j*2]   = __floats2half2_rn(v.x, v.y);
    dst[j*2+1] = __floats2half2_rn(v.z, v.w);
}

// ===========================================================================
// fp16 tensor-core GEMM (NT): BM=BN=128, BK=32, 3-stage, strength-reduced.
// (Measured plateau: 116.5us per 16384x1024x1024.)
// ===========================================================================
#define HSTR 40
#define HSTAGE (128*HSTR)
#define NSTG 3
#define GEMM_SMEM (NSTG*2*HSTAGE*(int)sizeof(__half))   // 61440 B

__global__ __launch_bounds__(256, 2) void h16_gemm_nt(
    const __half* __restrict__ A,
    const __half* __restrict__ B,
    const float* __restrict__ Cin,
    void* __restrict__ CoutV,
    int Nn, int K, int addC, int outHalf)
{
    __half* hsm = (__half*)gsm;
    const int tid  = threadIdx.x;
    const int lane = tid & 31;
    const int w    = tid >> 5;
    const int wm   = w >> 2;
    const int wn   = w & 3;
    const int gid  = lane >> 2;
    const int t4   = lane & 3;

    const int bm = blockIdx.y * 128;
    const int bn = blockIdx.x * 128;
    const uint32_t sb = (uint32_t)__cvta_generic_to_shared(hsm);

    float acc[4][4][4];
#pragma unroll
    for (int i = 0; i < 4; i++)
#pragma unroll
        for (int j = 0; j < 4; j++)
#pragma unroll
            for (int q = 0; q < 4; q++) acc[i][j][q] = 0.f;

    const int NIT = K / 32;

    const int cr = tid >> 2;
    const int cc = (tid & 3) * 8;
    const __half* gA0 = A + (size_t)(bm + cr) * K + cc;
    const __half* gA1 = A + (size_t)(bm + cr + 64) * K + cc;
    const __half* gB0 = B + (size_t)(bn + cr) * K + cc;
    const __half* gB1 = B + (size_t)(bn + cr + 64) * K + cc;
    const uint32_t sA0 = sb + (cr * HSTR + cc) * 2;
    const uint32_t sA1 = sb + ((cr + 64) * HSTR + cc) * 2;
    const uint32_t sB0 = sb + (NSTG*HSTAGE + cr * HSTR + cc) * 2;
    const uint32_t sB1 = sb + (NSTG*HSTAGE + (cr + 64) * HSTR + cc) * 2;

    auto copy_stage = [&](int it, int st) {
        const uint32_t so = (uint32_t)(st * HSTAGE) * 2;
        const int ko = it * 32;
        cp16s(sA0 + so, gA0 + ko);
        cp16s(sA1 + so, gA1 + ko);
        cp16s(sB0 + so, gB0 + ko);
        cp16s(sB1 + so, gB1 + ko);
    };

    copy_stage(0, 0);
    asm volatile("cp.async.commit_group;");
    copy_stage(1, 1);
    asm volatile("cp.async.commit_group;");

    const int lrow = lane & 15;
    const int lcol = (lane >> 4) * 8;
    uint32_t aoff[4], boff[2];
#pragma unroll
    for (int i = 0; i < 4; i++)
        aoff[i] = sb + ((wm*64 + i*16 + lrow) * HSTR + lcol) * 2;
#pragma unroll
    for (int p = 0; p < 2; p++)
        boff[p] = sb + (NSTG*HSTAGE + (wn*32 + p*16 + lrow) * HSTR + lcol) * 2;

    for (int it = 0; it < NIT; it++) {
        asm volatile("cp.async.wait_group 1;");
        __syncthreads();
        const uint32_t so = (uint32_t)((it % NSTG) * HSTAGE) * 2;

#pragma unroll
        for (int kk = 0; kk < 2; kk++) {
            const uint32_t ko = so + kk * 32;
            uint32_t af[4][4], bf[4][2];
#pragma unroll
            for (int i = 0; i < 4; i++)
                ldsm4(aoff[i] + ko, af[i][0], af[i][1], af[i][2], af[i][3]);
#pragma unroll
            for (int p = 0; p < 2; p++) {
                uint32_t r0, r1, r2, r3;
                ldsm4(boff[p] + ko, r0, r1, r2, r3);
                bf[2*p  ][0] = r0; bf[2*p+1][0] = r1;
                bf[2*p  ][1] = r2; bf[2*p+1][1] = r3;
            }
#pragma unroll
            for (int i = 0; i < 4; i++)
#pragma unroll
                for (int j = 0; j < 4; j++)
                    mma_f16(acc[i][j], af[i][0], af[i][1], af[i][2], af[i][3],
                            bf[j][0], bf[j][1]);
        }
        if (it + 2 < NIT) copy_stage(it + 2, (it + 2) % NSTG);
        asm volatile("cp.async.commit_group;");
    }

#pragma unroll
    for (int i = 0; i < 4; i++) {
        int row = bm + wm*64 + i*16 + gid;
#pragma unroll
        for (int j = 0; j < 4; j++) {
            int col = bn + wn*32 + j*8 + t4*2;
            float2 r01 = make_float2(acc[i][j][0], acc[i][j][1]);
            float2 r23 = make_float2(acc[i][j][2], acc[i][j][3]);
            if (addC) {
                float2 c01 = *(const float2*)&Cin[(size_t)row*Nn + col];
                float2 c23 = *(const float2*)&Cin[(size_t)(row+8)*Nn + col];
                r01.x += c01.x; r01.y += c01.y;
                r23.x += c23.x; r23.y += c23.y;
            }
            if (outHalf) {
                __half* Ch = (__half*)CoutV;
                *(__half2*)&Ch[(size_t)row*Nn + col]     = __floats2half2_rn(r01.x, r01.y);
                *(__half2*)&Ch[(size_t)(row+8)*Nn + col] = __floats2half2_rn(r23.x, r23.y);
            } else {
                float* Cf = (float*)CoutV;
                *(float2*)&Cf[(size_t)row*Nn + col]     = r01;
                *(float2*)&Cf[(size_t)(row+8)*Nn + col] = r23;
            }
        }
    }
}

// ===========================================================================
// Scan phase A (tensor cores, 128 thr = 4 warps, one chunk per block).
// 65-row rkw tile (wk = row c, rk = row c+1); S masked -> smem fp16;
// intra = alpha*S@v -> fp16; vg overwrites S; Z = vg^T@wk -> fp16.
// ===========================================================================
#define TSTR 72
#define PA_SMEM ((193*TSTR)*2 + 256)
#define PC_SMEM (2*64*TSTR*2 + 64*4)

__global__ __launch_bounds__(128) void scan_phaseA_mma(
    const __half* __restrict__ outh, const __half* __restrict__ vh,
    const float* __restrict__ decay, const float* __restrict__ log_alpha,
    __half* __restrict__ intra, __half* __restrict__ Zh)
{
    __half* sRKW = (__half*)gsm;            // 65 rows
    __half* sV   = sRKW + 65*TSTR;          // 64 rows
    __half* sS   = sV   + 64*TSTR;          // 64 rows (S, later vg)
    float*  sgp  = (float*)(sS + 64*TSTR);

    const int tid = threadIdx.x, lane = tid & 31, w = tid >> 5;
    const int chunk = blockIdx.x, bh = blockIdx.y;
    const int b = bh >> 4, h = bh & 15;
    const float gamma = 1.f/(1.f+expf(-decay[h]));
    const float alpha = expf(log_alpha[h]);
    if (tid < 64) sgp[tid] = powf(gamma, (float)tid);

    const int t0 = chunk*64;
    const __half* rbase = outh + ((size_t)b*Tt + t0)*Dd + h*64;
    const __half* vbase = vh   + ((size_t)b*Tt + t0)*Dd + h*64;

#pragma unroll
    for (int i = 0; i < 5; i++) {
        int idx = tid + i*128;
        if (idx < 520) {
            int r = idx >> 3;
            int c8 = (idx & 7)*8;
            long gr = (long)r - 1;
            if (t0 + (int)gr < 0) gr = 0;
            cp16g(sRKW + r*TSTR + c8, rbase + gr*(long)Dd + c8);
        }
    }
#pragma unroll
    for (int i = 0; i < 4; i++) {
        int idx = tid + i*128;
        int r = idx >> 3;
        int c8 = (idx & 7)*8;
        cp16g(sV + r*TSTR + c8, vbase + (size_t)r*Dd + c8);
    }
    asm volatile("cp.async.commit_group;");
    asm volatile("cp.async.wait_group 0;");
    __syncthreads();
    if (chunk == 0 && tid < 8)
        *(uint4*)(sRKW + tid*8) = make_uint4(0u,0u,0u,0u);
    __syncthreads();

    const uint32_t sb  = (uint32_t)__cvta_generic_to_shared((void*)sRKW);
    const uint32_t aWK = sb;
    const uint32_t aRK = sb + TSTR*2;
    const uint32_t aV  = sb + 65*TSTR*2;
    const uint32_t aS  = sb + (65+64)*TSTR*2;

    const int lr = lane & 15;
    const int lc = (lane >> 4) * 8;
    const int trr = (lane & 7) + 8*(lane >> 4);
    const int trc = 8*((lane >> 3) & 1);
    const int gid = lane >> 2, t4 = lane & 3;
    const int cc0 = 16*w + gid;

    // ---- S = rk @ wk^T ----
    {
        float acc[8][4];
#pragma unroll
        for (int n = 0; n < 8; n++)
            acc[n][0]=acc[n][1]=acc[n][2]=acc[n][3]=0.f;
#pragma unroll
        for (int k = 0; k < 4; k++) {
            int k0 = k*16;
            uint32_t a0,a1,a2,a3;
            ldsm4(aRK + ((16*w + lr)*TSTR + k0 + lc)*2, a0,a1,a2,a3);
#pragma unroll
            for (int np = 0; np < 4; np++) {
                uint32_t b0,b1,b2,b3;
                ldsm4(aWK + ((np*16 + lr)*TSTR + k0 + lc)*2, b0,b1,b2,b3);
                mma_f16(acc[2*np],   a0,a1,a2,a3, b0,b2);
                mma_f16(acc[2*np+1], a0,a1,a2,a3, b1,b3);
            }
        }
#pragma unroll
        for (int nt = 0; nt < 8; nt++) {
            int kk = nt*8 + 2*t4;
            float m00 = (cc0   > kk  ) ? sgp[cc0-1-kk] : 0.f;
            float m01 = (cc0   > kk+1) ? sgp[cc0-2-kk] : 0.f;
            float m10 = (cc0+8 > kk  ) ? sgp[cc0+7-kk] : 0.f;
            float m11 = (cc0+8 > kk+1) ? sgp[cc0+6-kk] : 0.f;
            *(__half2*)(sS + (size_t)cc0*TSTR + kk) =
                __floats2half2_rn(acc[nt][0]*m00, acc[nt][1]*m01);
            *(__half2*)(sS + (size_t)(cc0+8)*TSTR + kk) =
                __floats2half2_rn(acc[nt][2]*m10, acc[nt][3]*m11);
        }
    }
    __syncthreads();

    // ---- intra = S @ v ----
    {
        float iacc[8][4];
#pragma unroll
        for (int n = 0; n < 8; n++)
            iacc[n][0]=iacc[n][1]=iacc[n][2]=iacc[n][3]=0.f;
#pragma unroll
        for (int k = 0; k < 4; k++) {
            int k0 = k*16;
            uint32_t a0,a1,a2,a3;
            ldsm4(aS + ((16*w + lr)*TSTR + k0 + lc)*2, a0,a1,a2,a3);
#pragma unroll
            for (int np = 0; np < 4; np++) {
                uint32_t b0,b1,b2,b3;
                ldsm4t(aV + ((k0 + trr)*TSTR + np*16 + trc)*2, b0,b1,b2,b3);
                mma_f16(iacc[2*np],   a0,a1,a2,a3, b0,b2);
                mma_f16(iacc[2*np+1], a0,a1,a2,a3, b1,b3);
            }
        }
        __half* ibase = intra + ((size_t)b*Tt + t0)*Dd + h*64;
#pragma unroll
        for (int nt = 0; nt < 8; nt++) {
            int col = nt*8 + 2*t4;
            *(__half2*)&ibase[(size_t)cc0*Dd + col] =
                __floats2half2_rn(alpha*iacc[nt][0], alpha*iacc[nt][1]);
            *(__half2*)&ibase[(size_t)(cc0+8)*Dd + col] =
                __floats2half2_rn(alpha*iacc[nt][2], alpha*iacc[nt][3]);
        }
    }
    __syncthreads();

    // vg -> sS region
#pragma unroll
    for (int i = 0; i < 16; i++) {
        int idx = tid + i*128;
        int row = idx >> 5, col2 = idx & 31;
        __half2 g2 = __float2half2_rn(sgp[63 - row]);
        ((__half2*)sS)[row*(TSTR/2) + col2] =
            __hmul2(((__half2*)sV)[row*(TSTR/2) + col2], g2);
    }
    __syncthreads();

    // ---- Z = vg^T @ wk -> fp16 ----
    {
        float zacc[8][4];
#pragma unroll
        for (int n = 0; n < 8; n++)
            zacc[n][0]=zacc[n][1]=zacc[n][2]=zacc[n][3]=0.f;
#pragma unroll
        for (int k = 0; k < 4; k++) {
            int k0 = k*16;
            uint32_t a0,a1,a2,a3;
            ldsm4t(aS + ((k0 + trr)*TSTR + 16*w + trc)*2, a0,a1,a2,a3);
#pragma unroll
            for (int np = 0; np < 4; np++) {
                uint32_t b0,b1,b2,b3;
                ldsm4t(aWK + ((k0 + trr)*TSTR + np*16 + trc)*2, b0,b1,b2,b3);
                mma_f16(zacc[2*np],   a0,a1,a2,a3, b0,b2);
                mma_f16(zacc[2*np+1], a0,a1,a2,a3, b1,b3);
            }
        }
        __half* zbase = Zh + ((size_t)bh*nCh + chunk)*4096;
#pragma unroll
        for (int nt = 0; nt < 8; nt++) {
            int col = nt*8 + 2*t4;
            *(__half2*)&zbase[cc0*64 + col] =
                __floats2half2_rn(zacc[nt][0], zacc[nt][1]);
            *(__half2*)&zbase[(cc0+8)*64 + col] =
                __floats2half2_rn(zacc[nt][2], zacc[nt][3]);
        }
    }
}

// ===========================================================================
// Scan phase B: decayed exclusive prefix, 2 elems/thread (__half2), fp32
// accumulators, unroll 16 (MLP). grid (8, BHt) x 256 thr.
// ===========================================================================
__global__ __launch_bounds__(256) void scan_phaseB(
    const float* __restrict__ decay, const __half* __restrict__ Zh,
    __half* __restrict__ Wh)
{
    const int bh = blockIdx.y, h = bh & 15;
    const int e2 = (blockIdx.x * 256 + threadIdx.x) * 2;
    const float gamma = 1.f/(1.f+expf(-decay[h]));
    const float gC = powf(gamma, 64.f);
    float w0 = 0.f, w1 = 0.f;
    size_t base = (size_t)bh*nCh*4096 + e2;
    const __half2* zp = (const __half2*)(Zh + base);
    __half2* wp = (__half2*)(Wh + base);
#pragma unroll 16
    for (int n = 0; n < nCh; n++) {
        __half2 zu = zp[n*2048];
        wp[n*2048] = __floats2half2_rn(w0, w1);
        float2 z = __half22float2(zu);
        w0 = gC*w0 + z.x;
        w1 = gC*w1 + z.y;
    }
}

// ===========================================================================
// Scan phase C (tensor cores, 128 thr, one chunk per block):
//   inter = rk @ W^T ; reads_h = fp16(intra + alpha*g_p[c]*inter)
// ===========================================================================
__global__ __launch_bounds__(128) void scan_phaseC_mma(
    const __half* __restrict__ outh, const __half* __restrict__ Wh,
    const float* __restrict__ decay, const float* __restrict__ log_alpha,
    const __half* __restrict__ intra, __half* __restrict__ readsh)
{
    __half* sRK = (__half*)gsm;
    __half* sW  = sRK + 64*TSTR;
    float*  sgp = (float*)(sW + 64*TSTR);

    const int tid = threadIdx.x, lane = tid & 31, w = tid >> 5;
    const int chunk = blockIdx.x, bh = blockIdx.y;
    const int b = bh >> 4, h = bh & 15;
    const float gamma = 1.f/(1.f+expf(-decay[h]));
    const float alpha = expf(log_alpha[h]);
    if (tid < 64) sgp[tid] = powf(gamma, (float)tid);

    const int t0 = chunk*64;
    const __half* rbase = outh + ((size_t)b*Tt + t0)*Dd + h*64;
    const __half* wsrc  = Wh + ((size_t)bh*nCh + chunk)*4096;

#pragma unroll
    for (int i = 0; i < 4; i++) {
        int idx = tid + i*128;
        int r = idx >> 3;
        int c8 = (idx & 7)*8;
        cp16g(sRK + r*TSTR + c8, rbase + (size_t)r*Dd + c8);
        cp16g(sW  + r*TSTR + c8, wsrc + r*64 + c8);
    }
    asm volatile("cp.async.commit_group;");
    asm volatile("cp.async.wait_group 0;");
    __syncthreads();

    const uint32_t sb  = (uint32_t)__cvta_generic_to_shared((void*)sRK);
    const uint32_t aRK = sb;
    const uint32_t aW  = sb + 64*TSTR*2;

    const int lr = lane & 15;
    const int lc = (lane >> 4) * 8;
    const int gid = lane >> 2, t4 = lane & 3;
    const int cc0 = 16*w + gid;

    float acc[8][4];
#pragma unroll
    for (int n = 0; n < 8; n++)
        acc[n][0]=acc[n][1]=acc[n][2]=acc[n][3]=0.f;
#pragma unroll
    for (int k = 0; k < 4; k++) {
        int k0 = k*16;
        uint32_t a0,a1,a2,a3;
        ldsm4(aRK + ((16*w + lr)*TSTR + k0 + lc)*2, a0,a1,a2,a3);
#pragma unroll
        for (int np = 0; np < 4; np++) {
            uint32_t b0,b1,b2,b3;
            ldsm4(aW + ((np*16 + lr)*TSTR + k0 + lc)*2, b0,b1,b2,b3);
            mma_f16(acc[2*np],   a0,a1,a2,a3, b0,b2);
            mma_f16(acc[2*np+1], a0,a1,a2,a3, b1,b3);
        }
    }

    const __half* ibase = intra + ((size_t)b*Tt + t0)*Dd + h*64;
    __half* obase = readsh + ((size_t)b*Tt + t0)*Dd + h*64;
    const float gp0 = alpha * sgp[cc0];
    const float gp1 = alpha * sgp[cc0 + 8];
#pragma unroll
    for (int nt = 0; nt < 8; nt++) {
        int col = nt*8 + 2*t4;
        float2 i0 = __half22float2(*(const __half2*)&ibase[(size_t)cc0*Dd + col]);
        float2 i1 = __half22float2(*(const __half2*)&ibase[(size_t)(cc0+8)*Dd + col]);
        *(__half2*)&obase[(size_t)cc0*Dd + col] =
            __floats2half2_rn(i0.x + gp0*acc[nt][0], i0.y + gp0*acc[nt][1]);
        *(__half2*)&obase[(size_t)(cc0+8)*Dd + col] =
            __floats2half2_rn(i1.x + gp1*acc[nt][2], i1.y + gp1*acc[nt][3]);
    }
}

// ===========================================================================
extern "C" void kernel_launch(void* const* d_in, const int* in_sizes, int n_in,
                              void* d_out, int out_size)
{
    const float* outp      = (const float*)d_in[0];
    const float* W_write   = (const float*)d_in[1];
    const float* W_read    = (const float*)d_in[2];
    const float* decay     = (const float*)d_in[3];
    const float* log_alpha = (const float*)d_in[4];
    float* result = (float*)d_out;

    __half *outh, *wwh, *wrh, *vh, *ih, *zh, *whs, *readsh;
    cudaGetSymbolAddress((void**)&outh,   g_out_h);
    cudaGetSymbolAddress((void**)&wwh,    g_Ww_h);
    cudaGetSymbolAddress((void**)&wrh,    g_Wr_h);
    cudaGetSymbolAddress((void**)&vh,     g_v_h);
    cudaGetSymbolAddress((void**)&ih,     g_intra_h);
    cudaGetSymbolAddress((void**)&zh,     g_Z_h);
    cudaGetSymbolAddress((void**)&whs,    g_W_h);
    cudaGetSymbolAddress((void**)&readsh, g_reads_h);

    cudaFuncSetAttribute(h16_gemm_nt,
        cudaFuncAttributeMaxDynamicSharedMemorySize, GEMM_SMEM);
    cudaFuncSetAttribute(scan_phaseA_mma,
        cudaFuncAttributeMaxDynamicSharedMemorySize, PA_SMEM);
    cudaFuncSetAttribute(scan_phaseC_mma,
        cudaFuncAttributeMaxDynamicSharedMemorySize, PC_SMEM);

    // fused conversions (one launch)
    const int totN4 = N4_OUT + 2*N4_W;
    cvt_all_f2h<<<(totN4 + 255)/256, 256>>>(
        (const float4*)outp, (const float4*)W_write, (const float4*)W_read,
        (__half2*)outh, (__half2*)wwh, (__half2*)wrh);

    dim3 gemm_grid(Dd/128, Mrows/128);   // (8, 128)

    // GEMM1: v_h = fp16(out @ W_write^T)
    h16_gemm_nt<<<gemm_grid, 256, GEMM_SMEM>>>(outh, wwh, nullptr, vh,
                                               Dd, Dd, 0, 1);
    // Scan
    scan_phaseA_mma<<<dim3(nCh, BHt), 128, PA_SMEM>>>(outh, vh, decay,
                                                      log_alpha, ih, zh);
    scan_phaseB<<<dim3(8, BHt), 256>>>(decay, zh, whs);
    scan_phaseC_mma<<<dim3(nCh, BHt), 128, PC_SMEM>>>(outh, whs, decay,
                                                      log_alpha, ih, readsh);
    // GEMM2: result = out + reads @ W_read^T (fp32 out)
    h16_gemm_nt<<<gemm_grid, 256, GEMM_SMEM>>>(readsh, wrh, outp, result,
                                               Dd, Dd, 1, 0);
}

// round 17
// speedup vs baseline: 1.0289x; 1.0003x over previous
#include <cuda_runtime.h>
#include <cuda_fp16.h>
#include <cstdint>

// Problem constants
#define Bb 4
#define Tt 4096
#define Dd 1024
#define Hh 16
#define Cc 64
#define nCh 64
#define BHt 64
#define Mrows (Bb*Tt)   // 16384

// Scratch (__device__ globals per allocation rules)
__device__ __half g_out_h[Bb*Tt*Dd];     // fp16 input
__device__ __half g_Ww_h[Dd*Dd];
__device__ __half g_Wr_h[Dd*Dd];
__device__ __half g_v_h[Bb*Tt*Dd];       // fp16 write projection
__device__ __half g_intra_h[Bb*Tt*Dd];   // alpha*intra fp16
__device__ __half g_Z_h[BHt*nCh*64*64];  // fp16 chunk increments Z
__device__ __half g_W_h[BHt*nCh*64*64];  // fp16 per-chunk W states
__device__ __half g_reads_h[Bb*Tt*Dd];   // fp16 reads (GEMM2 A)

extern __shared__ float gsm[];

// ---------------------------------------------------------------------------
// helpers
// ---------------------------------------------------------------------------
__device__ __forceinline__ void cp16g(void* sdst, const void* gsrc) {
    unsigned s = (unsigned)__cvta_generic_to_shared(sdst);
    asm volatile("cp.async.ca.shared.global [%0], [%1], 16;" :: "r"(s), "l"(gsrc));
}
__device__ __forceinline__ void cp16s(uint32_t sdst, const void* gsrc) {
    asm volatile("cp.async.ca.shared.global [%0], [%1], 16;" :: "r"(sdst), "l"(gsrc));
}
__device__ __forceinline__ void ldsm4(uint32_t addr, uint32_t& r0, uint32_t& r1,
                                      uint32_t& r2, uint32_t& r3) {
    asm volatile("ldmatrix.sync.aligned.m8n8.x4.shared.b16 {%0,%1,%2,%3}, [%4];"
        : "=r"(r0), "=r"(r1), "=r"(r2), "=r"(r3) : "r"(addr));
}
__device__ __forceinline__ void ldsm4t(uint32_t addr, uint32_t& r0, uint32_t& r1,
                                       uint32_t& r2, uint32_t& r3) {
    asm volatile("ldmatrix.sync.aligned.m8n8.x4.trans.shared.b16 {%0,%1,%2,%3}, [%4];"
        : "=r"(r0), "=r"(r1), "=r"(r2), "=r"(r3) : "r"(addr));
}
__device__ __forceinline__ void mma_f16(float c[4], uint32_t a0, uint32_t a1,
                                        uint32_t a2, uint32_t a3,
                                        uint32_t b0, uint32_t b1) {
    asm volatile(
        "mma.sync.aligned.m16n8k16.row.col.f32.f16.f16.f32 "
        "{%0,%1,%2,%3}, {%4,%5,%6,%7}, {%8,%9}, {%0,%1,%2,%3};"
        : "+f"(c[0]), "+f"(c[1]), "+f"(c[2]), "+f"(c[3])
        : "r"(a0), "r"(a1), "r"(a2), "r"(a3), "r"(b0), "r"(b1));
}

// ---------------------------------------------------------------------------
// fused fp32 -> fp16 conversion for out + W_write + W_read (one launch)
// ---------------------------------------------------------------------------
#define N4_OUT (Bb*Tt*Dd/4)   // 1048576
#define N4_W   (Dd*Dd/4)      // 262144
__global__ __launch_bounds__(256) void cvt_all_f2h(
    const float4* __restrict__ outp, const float4* __restrict__ Ww,
    const float4* __restrict__ Wr, __half2* __restrict__ outh,
    __half2* __restrict__ wwh, __half2* __restrict__ wrh)
{
    int i = blockIdx.x * blockDim.x + threadIdx.x;
    const float4* src;
    __half2* dst;
    int j;
    if (i < N4_OUT)             { src = outp; dst = outh; j = i; }
    else if (i < N4_OUT + N4_W) { src = Ww;   dst = wwh;  j = i - N4_OUT; }
    else if (i < N4_OUT + 2*N4_W) { src = Wr; dst = wrh;  j = i - N4_OUT - N4_W; }
    else return;
    float4 v = src[j];
    dst[j*2]   = __floats2half2_rn(v.x, v.y);
    dst[j*2+1] = __floats2half2_rn(v.z, v.w);
}

// ===========================================================================
// fp16 tensor-core GEMM (NT): BM=BN=128, BK=32, 3-stage, strength-reduced.
// (Measured plateau: 116.5us per 16384x1024x1024.)
// ===========================================================================
#define HSTR 40
#define HSTAGE (128*HSTR)
#define NSTG 3
#define GEMM_SMEM (NSTG*2*HSTAGE*(int)sizeof(__half))   // 61440 B

__global__ __launch_bounds__(256, 2) void h16_gemm_nt(
    const __half* __restrict__ A,
    const __half* __restrict__ B,
    const float* __restrict__ Cin,
    void* __restrict__ CoutV,
    int Nn, int K, int addC, int outHalf)
{
    __half* hsm = (__half*)gsm;
    const int tid  = threadIdx.x;
    const int lane = tid & 31;
    const int w    = tid >> 5;
    const int wm   = w >> 2;
    const int wn   = w & 3;
    const int gid  = lane >> 2;
    const int t4   = lane & 3;

    const int bm = blockIdx.y * 128;
    const int bn = blockIdx.x * 128;
    const uint32_t sb = (uint32_t)__cvta_generic_to_shared(hsm);

    float acc[4][4][4];
#pragma unroll
    for (int i = 0; i < 4; i++)
#pragma unroll
        for (int j = 0; j < 4; j++)
#pragma unroll
            for (int q = 0; q < 4; q++) acc[i][j][q] = 0.f;

    const int NIT = K / 32;

    const int cr = tid >> 2;
    const int cc = (tid & 3) * 8;
    const __half* gA0 = A + (size_t)(bm + cr) * K + cc;
    const __half* gA1 = A + (size_t)(bm + cr + 64) * K + cc;
    const __half* gB0 = B + (size_t)(bn + cr) * K + cc;
    const __half* gB1 = B + (size_t)(bn + cr + 64) * K + cc;
    const uint32_t sA0 = sb + (cr * HSTR + cc) * 2;
    const uint32_t sA1 = sb + ((cr + 64) * HSTR + cc) * 2;
    const uint32_t sB0 = sb + (NSTG*HSTAGE + cr * HSTR + cc) * 2;
    const uint32_t sB1 = sb + (NSTG*HSTAGE + (cr + 64) * HSTR + cc) * 2;

    auto copy_stage = [&](int it, int st) {
        const uint32_t so = (uint32_t)(st * HSTAGE) * 2;
        const int ko = it * 32;
        cp16s(sA0 + so, gA0 + ko);
        cp16s(sA1 + so, gA1 + ko);
        cp16s(sB0 + so, gB0 + ko);
        cp16s(sB1 + so, gB1 + ko);
    };

    copy_stage(0, 0);
    asm volatile("cp.async.commit_group;");
    copy_stage(1, 1);
    asm volatile("cp.async.commit_group;");

    const int lrow = lane & 15;
    const int lcol = (lane >> 4) * 8;
    uint32_t aoff[4], boff[2];
#pragma unroll
    for (int i = 0; i < 4; i++)
        aoff[i] = sb + ((wm*64 + i*16 + lrow) * HSTR + lcol) * 2;
#pragma unroll
    for (int p = 0; p < 2; p++)
        boff[p] = sb + (NSTG*HSTAGE + (wn*32 + p*16 + lrow) * HSTR + lcol) * 2;

    for (int it = 0; it < NIT; it++) {
        asm volatile("cp.async.wait_group 1;");
        __syncthreads();
        const uint32_t so = (uint32_t)((it % NSTG) * HSTAGE) * 2;

#pragma unroll
        for (int kk = 0; kk < 2; kk++) {
            const uint32_t ko = so + kk * 32;
            uint32_t af[4][4], bf[4][2];
#pragma unroll
            for (int i = 0; i < 4; i++)
                ldsm4(aoff[i] + ko, af[i][0], af[i][1], af[i][2], af[i][3]);
#pragma unroll
            for (int p = 0; p < 2; p++) {
                uint32_t r0, r1, r2, r3;
                ldsm4(boff[p] + ko, r0, r1, r2, r3);
                bf[2*p  ][0] = r0; bf[2*p+1][0] = r1;
                bf[2*p  ][1] = r2; bf[2*p+1][1] = r3;
            }
#pragma unroll
            for (int i = 0; i < 4; i++)
#pragma unroll
                for (int j = 0; j < 4; j++)
                    mma_f16(acc[i][j], af[i][0], af[i][1], af[i][2], af[i][3],
                            bf[j][0], bf[j][1]);
        }
        if (it + 2 < NIT) copy_stage(it + 2, (it + 2) % NSTG);
        asm volatile("cp.async.commit_group;");
    }

#pragma unroll
    for (int i = 0; i < 4; i++) {
        int row = bm + wm*64 + i*16 + gid;
#pragma unroll
        for (int j = 0; j < 4; j++) {
            int col = bn + wn*32 + j*8 + t4*2;
            float2 r01 = make_float2(acc[i][j][0], acc[i][j][1]);
            float2 r23 = make_float2(acc[i][j][2], acc[i][j][3]);
            if (addC) {
                float2 c01 = *(const float2*)&Cin[(size_t)row*Nn + col];
                float2 c23 = *(const float2*)&Cin[(size_t)(row+8)*Nn + col];
                r01.x += c01.x; r01.y += c01.y;
                r23.x += c23.x; r23.y += c23.y;
            }
            if (outHalf) {
                __half* Ch = (__half*)CoutV;
                *(__half2*)&Ch[(size_t)row*Nn + col]     = __floats2half2_rn(r01.x, r01.y);
                *(__half2*)&Ch[(size_t)(row+8)*Nn + col] = __floats2half2_rn(r23.x, r23.y);
            } else {
                float* Cf = (float*)CoutV;
                *(float2*)&Cf[(size_t)row*Nn + col]     = r01;
                *(float2*)&Cf[(size_t)(row+8)*Nn + col] = r23;
            }
        }
    }
}

// ===========================================================================
// Scan phase A (tensor cores, 128 thr = 4 warps, one chunk per block).
// 65-row rkw tile (wk = row c, rk = row c+1); S masked -> smem fp16;
// intra = alpha*S@v -> fp16; vg overwrites S; Z = vg^T@wk -> fp16.
// ===========================================================================
#define TSTR 72
#define PA_SMEM ((193*TSTR)*2 + 256)
#define PC_SMEM (2*64*TSTR*2 + 64*4)

__global__ __launch_bounds__(128) void scan_phaseA_mma(
    const __half* __restrict__ outh, const __half* __restrict__ vh,
    const float* __restrict__ decay, const float* __restrict__ log_alpha,
    __half* __restrict__ intra, __half* __restrict__ Zh)
{
    __half* sRKW = (__half*)gsm;            // 65 rows
    __half* sV   = sRKW + 65*TSTR;          // 64 rows
    __half* sS   = sV   + 64*TSTR;          // 64 rows (S, later vg)
    float*  sgp  = (float*)(sS + 64*TSTR);

    const int tid = threadIdx.x, lane = tid & 31, w = tid >> 5;
    const int chunk = blockIdx.x, bh = blockIdx.y;
    const int b = bh >> 4, h = bh & 15;
    const float gamma = 1.f/(1.f+expf(-decay[h]));
    const float alpha = expf(log_alpha[h]);
    if (tid < 64) sgp[tid] = powf(gamma, (float)tid);

    const int t0 = chunk*64;
    const __half* rbase = outh + ((size_t)b*Tt + t0)*Dd + h*64;
    const __half* vbase = vh   + ((size_t)b*Tt + t0)*Dd + h*64;

#pragma unroll
    for (int i = 0; i < 5; i++) {
        int idx = tid + i*128;
        if (idx < 520) {
            int r = idx >> 3;
            int c8 = (idx & 7)*8;
            long gr = (long)r - 1;
            if (t0 + (int)gr < 0) gr = 0;
            cp16g(sRKW + r*TSTR + c8, rbase + gr*(long)Dd + c8);
        }
    }
#pragma unroll
    for (int i = 0; i < 4; i++) {
        int idx = tid + i*128;
        int r = idx >> 3;
        int c8 = (idx & 7)*8;
        cp16g(sV + r*TSTR + c8, vbase + (size_t)r*Dd + c8);
    }
    asm volatile("cp.async.commit_group;");
    asm volatile("cp.async.wait_group 0;");
    __syncthreads();
    if (chunk == 0 && tid < 8)
        *(uint4*)(sRKW + tid*8) = make_uint4(0u,0u,0u,0u);
    __syncthreads();

    const uint32_t sb  = (uint32_t)__cvta_generic_to_shared((void*)sRKW);
    const uint32_t aWK = sb;
    const uint32_t aRK = sb + TSTR*2;
    const uint32_t aV  = sb + 65*TSTR*2;
    const uint32_t aS  = sb + (65+64)*TSTR*2;

    const int lr = lane & 15;
    const int lc = (lane >> 4) * 8;
    const int trr = (lane & 7) + 8*(lane >> 4);
    const int trc = 8*((lane >> 3) & 1);
    const int gid = lane >> 2, t4 = lane & 3;
    const int cc0 = 16*w + gid;

    // ---- S = rk @ wk^T ----
    {
        float acc[8][4];
#pragma unroll
        for (int n = 0; n < 8; n++)
            acc[n][0]=acc[n][1]=acc[n][2]=acc[n][3]=0.f;
#pragma unroll
        for (int k = 0; k < 4; k++) {
            int k0 = k*16;
            uint32_t a0,a1,a2,a3;
            ldsm4(aRK + ((16*w + lr)*TSTR + k0 + lc)*2, a0,a1,a2,a3);
#pragma unroll
            for (int np = 0; np < 4; np++) {
                uint32_t b0,b1,b2,b3;
                ldsm4(aWK + ((np*16 + lr)*TSTR + k0 + lc)*2, b0,b1,b2,b3);
                mma_f16(acc[2*np],   a0,a1,a2,a3, b0,b2);
                mma_f16(acc[2*np+1], a0,a1,a2,a3, b1,b3);
            }
        }
#pragma unroll
        for (int nt = 0; nt < 8; nt++) {
            int kk = nt*8 + 2*t4;
            float m00 = (cc0   > kk  ) ? sgp[cc0-1-kk] : 0.f;
            float m01 = (cc0   > kk+1) ? sgp[cc0-2-kk] : 0.f;
            float m10 = (cc0+8 > kk  ) ? sgp[cc0+7-kk] : 0.f;
            float m11 = (cc0+8 > kk+1) ? sgp[cc0+6-kk] : 0.f;
            *(__half2*)(sS + (size_t)cc0*TSTR + kk) =
                __floats2half2_rn(acc[nt][0]*m00, acc[nt][1]*m01);
            *(__half2*)(sS + (size_t)(cc0+8)*TSTR + kk) =
                __floats2half2_rn(acc[nt][2]*m10, acc[nt][3]*m11);
        }
    }
    __syncthreads();

    // ---- intra = S @ v ----
    {
        float iacc[8][4];
#pragma unroll
        for (int n = 0; n < 8; n++)
            iacc[n][0]=iacc[n][1]=iacc[n][2]=iacc[n][3]=0.f;
#pragma unroll
        for (int k = 0; k < 4; k++) {
            int k0 = k*16;
            uint32_t a0,a1,a2,a3;
            ldsm4(aS + ((16*w + lr)*TSTR + k0 + lc)*2, a0,a1,a2,a3);
#pragma unroll
            for (int np = 0; np < 4; np++) {
                uint32_t b0,b1,b2,b3;
                ldsm4t(aV + ((k0 + trr)*TSTR + np*16 + trc)*2, b0,b1,b2,b3);
                mma_f16(iacc[2*np],   a0,a1,a2,a3, b0,b2);
                mma_f16(iacc[2*np+1], a0,a1,a2,a3, b1,b3);
            }
        }
        __half* ibase = intra + ((size_t)b*Tt + t0)*Dd + h*64;
#pragma unroll
        for (int nt = 0; nt < 8; nt++) {
            int col = nt*8 + 2*t4;
            *(__half2*)&ibase[(size_t)cc0*Dd + col] =
                __floats2half2_rn(alpha*iacc[nt][0], alpha*iacc[nt][1]);
            *(__half2*)&ibase[(size_t)(cc0+8)*Dd + col] =
                __floats2half2_rn(alpha*iacc[nt][2], alpha*iacc[nt][3]);
        }
    }
    __syncthreads();

    // vg -> sS region
#pragma unroll
    for (int i = 0; i < 16; i++) {
        int idx = tid + i*128;
        int row = idx >> 5, col2 = idx & 31;
        __half2 g2 = __float2half2_rn(sgp[63 - row]);
        ((__half2*)sS)[row*(TSTR/2) + col2] =
            __hmul2(((__half2*)sV)[row*(TSTR/2) + col2], g2);
    }
    __syncthreads();

    // ---- Z = vg^T @ wk -> fp16 ----
    {
        float zacc[8][4];
#pragma unroll
        for (int n = 0; n < 8; n++)
            zacc[n][0]=zacc[n][1]=zacc[n][2]=zacc[n][3]=0.f;
#pragma unroll
        for (int k = 0; k < 4; k++) {
            int k0 = k*16;
            uint32_t a0,a1,a2,a3;
            ldsm4t(aS + ((k0 + trr)*TSTR + 16*w + trc)*2, a0,a1,a2,a3);
#pragma unroll
            for (int np = 0; np < 4; np++) {
                uint32_t b0,b1,b2,b3;
                ldsm4t(aWK + ((k0 + trr)*TSTR + np*16 + trc)*2, b0,b1,b2,b3);
                mma_f16(zacc[2*np],   a0,a1,a2,a3, b0,b2);
                mma_f16(zacc[2*np+1], a0,a1,a2,a3, b1,b3);
            }
        }
        __half* zbase = Zh + ((size_t)bh*nCh + chunk)*4096;
#pragma unroll
        for (int nt = 0; nt < 8; nt++) {
            int col = nt*8 + 2*t4;
            *(__half2*)&zbase[cc0*64 + col] =
                __floats2half2_rn(zacc[nt][0], zacc[nt][1]);
            *(__half2*)&zbase[(cc0+8)*64 + col] =
                __floats2half2_rn(zacc[nt][2], zacc[nt][3]);
        }
    }
}

// ===========================================================================
// Scan phase B: decayed exclusive prefix, 2 elems/thread (__half2), fp32
// accumulators, unroll 32 (MLP). grid (8, BHt) x 256 thr.
// ===========================================================================
__global__ __launch_bounds__(256) void scan_phaseB(
    const float* __restrict__ decay, const __half* __restrict__ Zh,
    __half* __restrict__ Wh)
{
    const int bh = blockIdx.y, h = bh & 15;
    const int e2 = (blockIdx.x * 256 + threadIdx.x) * 2;
    const float gamma = 1.f/(1.f+expf(-decay[h]));
    const float gC = powf(gamma, 64.f);
    float w0 = 0.f, w1 = 0.f;
    size_t base = (size_t)bh*nCh*4096 + e2;
    const __half2* zp = (const __half2*)(Zh + base);
    __half2* wp = (__half2*)(Wh + base);
#pragma unroll 32
    for (int n = 0; n < nCh; n++) {
        __half2 zu = zp[n*2048];
        wp[n*2048] = __floats2half2_rn(w0, w1);
        float2 z = __half22float2(zu);
        w0 = gC*w0 + z.x;
        w1 = gC*w1 + z.y;
    }
}

// ===========================================================================
// Scan phase C (tensor cores, 128 thr, one chunk per block):
//   inter = rk @ W^T ; reads_h = fp16(intra + alpha*g_p[c]*inter)
// ===========================================================================
__global__ __launch_bounds__(128) void scan_phaseC_mma(
    const __half* __restrict__ outh, const __half* __restrict__ Wh,
    const float* __restrict__ decay, const float* __restrict__ log_alpha,
    const __half* __restrict__ intra, __half* __restrict__ readsh)
{
    __half* sRK = (__half*)gsm;
    __half* sW  = sRK + 64*TSTR;
    float*  sgp = (float*)(sW + 64*TSTR);

    const int tid = threadIdx.x, lane = tid & 31, w = tid >> 5;
    const int chunk = blockIdx.x, bh = blockIdx.y;
    const int b = bh >> 4, h = bh & 15;
    const float gamma = 1.f/(1.f+expf(-decay[h]));
    const float alpha = expf(log_alpha[h]);
    if (tid < 64) sgp[tid] = powf(gamma, (float)tid);

    const int t0 = chunk*64;
    const __half* rbase = outh + ((size_t)b*Tt + t0)*Dd + h*64;
    const __half* wsrc  = Wh + ((size_t)bh*nCh + chunk)*4096;

#pragma unroll
    for (int i = 0; i < 4; i++) {
        int idx = tid + i*128;
        int r = idx >> 3;
        int c8 = (idx & 7)*8;
        cp16g(sRK + r*TSTR + c8, rbase + (size_t)r*Dd + c8);
        cp16g(sW  + r*TSTR + c8, wsrc + r*64 + c8);
    }
    asm volatile("cp.async.commit_group;");
    asm volatile("cp.async.wait_group 0;");
    __syncthreads();

    const uint32_t sb  = (uint32_t)__cvta_generic_to_shared((void*)sRK);
    const uint32_t aRK = sb;
    const uint32_t aW  = sb + 64*TSTR*2;

    const int lr = lane & 15;
    const int lc = (lane >> 4) * 8;
    const int gid = lane >> 2, t4 = lane & 3;
    const int cc0 = 16*w + gid;

    float acc[8][4];
#pragma unroll
    for (int n = 0; n < 8; n++)
        acc[n][0]=acc[n][1]=acc[n][2]=acc[n][3]=0.f;
#pragma unroll
    for (int k = 0; k < 4; k++) {
        int k0 = k*16;
        uint32_t a0,a1,a2,a3;
        ldsm4(aRK + ((16*w + lr)*TSTR + k0 + lc)*2, a0,a1,a2,a3);
#pragma unroll
        for (int np = 0; np < 4; np++) {
            uint32_t b0,b1,b2,b3;
            ldsm4(aW + ((np*16 + lr)*TSTR + k0 + lc)*2, b0,b1,b2,b3);
            mma_f16(acc[2*np],   a0,a1,a2,a3, b0,b2);
            mma_f16(acc[2*np+1], a0,a1,a2,a3, b1,b3);
        }
    }

    const __half* ibase = intra + ((size_t)b*Tt + t0)*Dd + h*64;
    __half* obase = readsh + ((size_t)b*Tt + t0)*Dd + h*64;
    const float gp0 = alpha * sgp[cc0];
    const float gp1 = alpha * sgp[cc0 + 8];
#pragma unroll
    for (int nt = 0; nt < 8; nt++) {
        int col = nt*8 + 2*t4;
        float2 i0 = __half22float2(*(const __half2*)&ibase[(size_t)cc0*Dd + col]);
        float2 i1 = __half22float2(*(const __half2*)&ibase[(size_t)(cc0+8)*Dd + col]);
        *(__half2*)&obase[(size_t)cc0*Dd + col] =
            __floats2half2_rn(i0.x + gp0*acc[nt][0], i0.y + gp0*acc[nt][1]);
        *(__half2*)&obase[(size_t)(cc0+8)*Dd + col] =
            __floats2half2_rn(i1.x + gp1*acc[nt][2], i1.y + gp1*acc[nt][3]);
    }
}

// ===========================================================================
extern "C" void kernel_launch(void* const* d_in, const int* in_sizes, int n_in,
                              void* d_out, int out_size)
{
    const float* outp      = (const float*)d_in[0];
    const float* W_write   = (const float*)d_in[1];
    const float* W_read    = (const float*)d_in[2];
    const float* decay     = (const float*)d_in[3];
    const float* log_alpha = (const float*)d_in[4];
    float* result = (float*)d_out;

    __half *outh, *wwh, *wrh, *vh, *ih, *zh, *whs, *readsh;
    cudaGetSymbolAddress((void**)&outh,   g_out_h);
    cudaGetSymbolAddress((void**)&wwh,    g_Ww_h);
    cudaGetSymbolAddress((void**)&wrh,    g_Wr_h);
    cudaGetSymbolAddress((void**)&vh,     g_v_h);
    cudaGetSymbolAddress((void**)&ih,     g_intra_h);
    cudaGetSymbolAddress((void**)&zh,     g_Z_h);
    cudaGetSymbolAddress((void**)&whs,    g_W_h);
    cudaGetSymbolAddress((void**)&readsh, g_reads_h);

    cudaFuncSetAttribute(h16_gemm_nt,
        cudaFuncAttributeMaxDynamicSharedMemorySize, GEMM_SMEM);
    cudaFuncSetAttribute(scan_phaseA_mma,
        cudaFuncAttributeMaxDynamicSharedMemorySize, PA_SMEM);
    cudaFuncSetAttribute(scan_phaseC_mma,
        cudaFuncAttributeMaxDynamicSharedMemorySize, PC_SMEM);

    // fused conversions (one launch)
    const int totN4 = N4_OUT + 2*N4_W;
    cvt_all_f2h<<<(totN4 + 255)/256, 256>>>(
        (const float4*)outp, (const float4*)W_write, (const float4*)W_read,
        (__half2*)outh, (__half2*)wwh, (__half2*)wrh);

    dim3 gemm_grid(Dd/128, Mrows/128);   // (8, 128)

    // GEMM1: v_h = fp16(out @ W_write^T)
    h16_gemm_nt<<<gemm_grid, 256, GEMM_SMEM>>>(outh, wwh, nullptr, vh,
                                               Dd, Dd, 0, 1);
    // Scan
    scan_phaseA_mma<<<dim3(nCh, BHt), 128, PA_SMEM>>>(outh, vh, decay,
                                                      log_alpha, ih, zh);
    scan_phaseB<<<dim3(8, BHt), 256>>>(decay, zh, whs);
    scan_phaseC_mma<<<dim3(nCh, BHt), 128, PC_SMEM>>>(outh, whs, decay,
                                                      log_alpha, ih, readsh);
    // GEMM2: result = out + reads @ W_read^T (fp32 out)
    h16_gemm_nt<<<gemm_grid, 256, GEMM_SMEM>>>(readsh, wrh, outp, result,
                                               Dd, Dd, 1, 0);
}